// round 1
// baseline (speedup 1.0000x reference)
#include <cuda_runtime.h>

#define N_NODES_C 50000
#define N_EDGES_C 800000
#define NODE_D_C  64
#define EDGE_D_C  32
#define ST_D_C    32
#define HID_C     128

#define TPB 256
#define TILE_E 32
#define TILE_N 32
#define N_TILES_E (N_EDGES_C / TILE_E)                     // 25000 exact
#define N_TILES_N ((N_NODES_C + TILE_N - 1) / TILE_N)      // 1563

// SMEM strides (floats), padded so LDS.128 across consecutive lanes hits
// distinct banks per 8-lane phase (stride mod 32 == 4).
#define W1_STRIDE 196   // 192 + 4   (msg layer1, K=192)
#define W2_STRIDE 132   // 128 + 4
#define W3_STRIDE 132
#define H_STRIDE  132
#define U1_STRIDE 100   // 96 + 4
#define U2_STRIDE 132

// Edge kernel smem: W1t + W2t + W3t + b1 + b2 + b3 + hbuf + src/dst
#define EDGE_SMEM_FLOATS (128*W1_STRIDE + 128*W2_STRIDE + 64*W3_STRIDE + 128 + 128 + 64 + TILE_E*H_STRIDE)
#define EDGE_SMEM_BYTES  (EDGE_SMEM_FLOATS*4 + 2*TILE_E*4)   // 220160 B

// Node kernel smem
#define NODE_SMEM_FLOATS (128*U1_STRIDE + 64*U2_STRIDE + 128 + 64 + TILE_N*H_STRIDE)
#define NODE_SMEM_BYTES  (NODE_SMEM_FLOATS*4)                // 102656 B

__device__ __forceinline__ float dot4(float4 a, float4 b) {
    return a.x*b.x + a.y*b.y + a.z*b.z + a.w*b.w;
}

// ---------------------------------------------------------------------------
// Edge path: per edge e:  msg_in = [nf[src](64), nf[dst](64), ef[e](32), st[src](32)]
//   h1 = relu(msg_in @ W1 + b1); h2 = relu(h1 @ W2 + b2); m = h2 @ W3 + b3
//   atomicAdd(agg[dst], m)
// Persistent CTAs, weights transposed in SMEM, 32-edge tiles.
// Thread microtile: layer1/2 -> 4 edges x 4 hidden; layer3 -> 2 edges x 1 float4.
// ---------------------------------------------------------------------------
__global__ __launch_bounds__(TPB, 1)
void edge_mlp_kernel(const float* __restrict__ nf,
                     const float* __restrict__ ef,
                     const float* __restrict__ stx,
                     const float* __restrict__ mW1, const float* __restrict__ mb1,
                     const float* __restrict__ mW2, const float* __restrict__ mb2,
                     const float* __restrict__ mW3, const float* __restrict__ mb3,
                     const int*   __restrict__ eidx,
                     float* __restrict__ agg)
{
    extern __shared__ float sm[];
    float* sW1t = sm;                              // [128][W1_STRIDE]  (Wt[j][k] = W1[k][j])
    float* sW2t = sW1t + 128 * W1_STRIDE;          // [128][W2_STRIDE]
    float* sW3t = sW2t + 128 * W2_STRIDE;          // [64][W3_STRIDE]
    float* sb1  = sW3t + 64 * W3_STRIDE;           // 128
    float* sb2  = sb1 + 128;                       // 128
    float* sb3  = sb2 + 128;                       // 64
    float* hbuf = sb3 + 64;                        // [TILE_E][H_STRIDE]
    int*   s_src = (int*)(hbuf + TILE_E * H_STRIDE);
    int*   s_dst = s_src + TILE_E;

    const int tid = threadIdx.x;

    // Load weights (transposed) once per block.
    for (int i = tid; i < 192 * 128; i += TPB) {
        int k = i >> 7, j = i & 127;
        sW1t[j * W1_STRIDE + k] = mW1[i];
    }
    for (int i = tid; i < 128 * 128; i += TPB) {
        int k = i >> 7, j = i & 127;
        sW2t[j * W2_STRIDE + k] = mW2[i];
    }
    for (int i = tid; i < 128 * 64; i += TPB) {
        int k = i >> 6, d = i & 63;
        sW3t[d * W3_STRIDE + k] = mW3[i];
    }
    if (tid < 128) { sb1[tid] = mb1[tid]; sb2[tid] = mb2[tid]; }
    if (tid < 64)  { sb3[tid] = mb3[tid]; }

    const int eg  = tid >> 5;    // 0..7   : edge group  (layers 1,2)
    const int jg  = tid & 31;    // 0..31  : hidden-unit lane
    const int d4  = tid & 15;    // 0..15  : output float4 index (layer 3)
    const int eg3 = tid >> 4;    // 0..15  : edge group (layer 3)

    const float4* nf4 = (const float4*)nf;
    const float4* ef4 = (const float4*)ef;
    const float4* st4 = (const float4*)stx;
    const float4* w1  = (const float4*)sW1t;   // row stride 49 float4
    const float4* w2  = (const float4*)sW2t;   // 33
    const float4* w3  = (const float4*)sW3t;   // 33
    const float4* h4  = (const float4*)hbuf;   // 33

    for (int tile = blockIdx.x; tile < N_TILES_E; tile += gridDim.x) {
        __syncthreads();   // prior tile fully consumed hbuf / s_src / s_dst
        if (tid < TILE_E) {
            int2 se = ((const int2*)eidx)[tile * TILE_E + tid];
            s_src[tid] = se.x;
            s_dst[tid] = se.y;
        }
        __syncthreads();

        const int e0 = eg * 4;
        int srcs[4], dsts[4];
        #pragma unroll
        for (int ei = 0; ei < 4; ei++) {
            srcs[ei] = s_src[e0 + ei];
            dsts[ei] = s_dst[e0 + ei];
        }

        // -------- layer 1: acc[ei][cj] = sum_k msg_in[e][k] * W1[k][j] --------
        float acc[4][4];
        #pragma unroll
        for (int a = 0; a < 4; a++)
            #pragma unroll
            for (int b = 0; b < 4; b++) acc[a][b] = 0.f;

        // region 1: nf[src], k chunks 0..15
        #pragma unroll 4
        for (int c = 0; c < 16; c++) {
            float4 xv[4];
            #pragma unroll
            for (int ei = 0; ei < 4; ei++) xv[ei] = nf4[srcs[ei] * 16 + c];
            #pragma unroll
            for (int cj = 0; cj < 4; cj++) {
                float4 w = w1[(jg + 32 * cj) * 49 + c];
                #pragma unroll
                for (int ei = 0; ei < 4; ei++) acc[ei][cj] += dot4(xv[ei], w);
            }
        }
        // region 2: nf[dst], k chunks 16..31
        #pragma unroll 4
        for (int c = 0; c < 16; c++) {
            float4 xv[4];
            #pragma unroll
            for (int ei = 0; ei < 4; ei++) xv[ei] = nf4[dsts[ei] * 16 + c];
            #pragma unroll
            for (int cj = 0; cj < 4; cj++) {
                float4 w = w1[(jg + 32 * cj) * 49 + (16 + c)];
                #pragma unroll
                for (int ei = 0; ei < 4; ei++) acc[ei][cj] += dot4(xv[ei], w);
            }
        }
        // region 3: ef[e], k chunks 32..39
        #pragma unroll 4
        for (int c = 0; c < 8; c++) {
            float4 xv[4];
            #pragma unroll
            for (int ei = 0; ei < 4; ei++)
                xv[ei] = ef4[(tile * TILE_E + e0 + ei) * 8 + c];
            #pragma unroll
            for (int cj = 0; cj < 4; cj++) {
                float4 w = w1[(jg + 32 * cj) * 49 + (32 + c)];
                #pragma unroll
                for (int ei = 0; ei < 4; ei++) acc[ei][cj] += dot4(xv[ei], w);
            }
        }
        // region 4: st[src], k chunks 40..47
        #pragma unroll 4
        for (int c = 0; c < 8; c++) {
            float4 xv[4];
            #pragma unroll
            for (int ei = 0; ei < 4; ei++) xv[ei] = st4[srcs[ei] * 8 + c];
            #pragma unroll
            for (int cj = 0; cj < 4; cj++) {
                float4 w = w1[(jg + 32 * cj) * 49 + (40 + c)];
                #pragma unroll
                for (int ei = 0; ei < 4; ei++) acc[ei][cj] += dot4(xv[ei], w);
            }
        }
        // bias + relu -> hbuf
        #pragma unroll
        for (int cj = 0; cj < 4; cj++) {
            float b = sb1[jg + 32 * cj];
            #pragma unroll
            for (int ei = 0; ei < 4; ei++)
                hbuf[(e0 + ei) * H_STRIDE + jg + 32 * cj] = fmaxf(acc[ei][cj] + b, 0.f);
        }
        __syncthreads();

        // -------- layer 2 --------
        float acc2[4][4];
        #pragma unroll
        for (int a = 0; a < 4; a++)
            #pragma unroll
            for (int b = 0; b < 4; b++) acc2[a][b] = 0.f;

        #pragma unroll 4
        for (int c = 0; c < 32; c++) {
            float4 xv[4];
            #pragma unroll
            for (int ei = 0; ei < 4; ei++) xv[ei] = h4[(e0 + ei) * 33 + c];
            #pragma unroll
            for (int cj = 0; cj < 4; cj++) {
                float4 w = w2[(jg + 32 * cj) * 33 + c];
                #pragma unroll
                for (int ei = 0; ei < 4; ei++) acc2[ei][cj] += dot4(xv[ei], w);
            }
        }
        __syncthreads();   // all reads of h1 done before overwrite
        #pragma unroll
        for (int cj = 0; cj < 4; cj++) {
            float b = sb2[jg + 32 * cj];
            #pragma unroll
            for (int ei = 0; ei < 4; ei++)
                hbuf[(e0 + ei) * H_STRIDE + jg + 32 * cj] = fmaxf(acc2[ei][cj] + b, 0.f);
        }
        __syncthreads();

        // -------- layer 3 + scatter: 2 edges x 4 outputs (one float4) per thread ----
        float acc3[2][4];
        #pragma unroll
        for (int a = 0; a < 2; a++)
            #pragma unroll
            for (int b = 0; b < 4; b++) acc3[a][b] = 0.f;

        const int e30 = eg3 * 2;
        #pragma unroll 4
        for (int c = 0; c < 32; c++) {
            float4 hv[2];
            #pragma unroll
            for (int ei = 0; ei < 2; ei++) hv[ei] = h4[(e30 + ei) * 33 + c];
            #pragma unroll
            for (int r = 0; r < 4; r++) {
                float4 w = w3[(d4 * 4 + r) * 33 + c];
                #pragma unroll
                for (int ei = 0; ei < 2; ei++) acc3[ei][r] += dot4(hv[ei], w);
            }
        }
        #pragma unroll
        for (int ei = 0; ei < 2; ei++) {
            float4 v;
            v.x = acc3[ei][0] + sb3[d4 * 4 + 0];
            v.y = acc3[ei][1] + sb3[d4 * 4 + 1];
            v.z = acc3[ei][2] + sb3[d4 * 4 + 2];
            v.w = acc3[ei][3] + sb3[d4 * 4 + 3];
            int dn = s_dst[e30 + ei];
            atomicAdd(((float4*)(agg + (size_t)dn * NODE_D_C)) + d4, v);
        }
    }
}

// ---------------------------------------------------------------------------
// Node path: out = nf + relu([nf, st] @ uW1 + ub1) @ uW2 + ub2
// ---------------------------------------------------------------------------
__global__ __launch_bounds__(TPB, 2)
void node_update_kernel(const float* __restrict__ nf,
                        const float* __restrict__ stx,
                        const float* __restrict__ uW1, const float* __restrict__ ub1,
                        const float* __restrict__ uW2, const float* __restrict__ ub2,
                        float* __restrict__ out_node)
{
    extern __shared__ float sm[];
    float* sU1t = sm;                          // [128][U1_STRIDE]
    float* sU2t = sU1t + 128 * U1_STRIDE;      // [64][U2_STRIDE]
    float* sb1  = sU2t + 64 * U2_STRIDE;       // 128
    float* sb2  = sb1 + 128;                   // 64
    float* hbuf = sb2 + 64;                    // [TILE_N][H_STRIDE]

    const int tid = threadIdx.x;
    for (int i = tid; i < 96 * 128; i += TPB) {
        int k = i >> 7, j = i & 127;
        sU1t[j * U1_STRIDE + k] = uW1[i];
    }
    for (int i = tid; i < 128 * 64; i += TPB) {
        int k = i >> 6, d = i & 63;
        sU2t[d * U2_STRIDE + k] = uW2[i];
    }
    if (tid < 128) sb1[tid] = ub1[tid];
    if (tid < 64)  sb2[tid] = ub2[tid];

    const int eg  = tid >> 5;
    const int jg  = tid & 31;
    const int d4  = tid & 15;
    const int eg3 = tid >> 4;

    const float4* nf4 = (const float4*)nf;
    const float4* st4 = (const float4*)stx;
    const float4* w1  = (const float4*)sU1t;   // row stride 25 float4
    const float4* w2  = (const float4*)sU2t;   // 33
    const float4* h4  = (const float4*)hbuf;   // 33
    float4* out4 = (float4*)out_node;

    for (int tile = blockIdx.x; tile < N_TILES_N; tile += gridDim.x) {
        __syncthreads();
        const int nbase = tile * TILE_N;

        // -------- layer 1 --------
        int nn[4];
        #pragma unroll
        for (int ei = 0; ei < 4; ei++) {
            int n = nbase + eg * 4 + ei;
            nn[ei] = (n < N_NODES_C) ? n : (N_NODES_C - 1);  // clamp: duplicate work, identical values
        }
        float acc[4][4];
        #pragma unroll
        for (int a = 0; a < 4; a++)
            #pragma unroll
            for (int b = 0; b < 4; b++) acc[a][b] = 0.f;

        #pragma unroll 4
        for (int c = 0; c < 16; c++) {   // nf region, k chunks 0..15
            float4 xv[4];
            #pragma unroll
            for (int ei = 0; ei < 4; ei++) xv[ei] = nf4[nn[ei] * 16 + c];
            #pragma unroll
            for (int cj = 0; cj < 4; cj++) {
                float4 w = w1[(jg + 32 * cj) * 25 + c];
                #pragma unroll
                for (int ei = 0; ei < 4; ei++) acc[ei][cj] += dot4(xv[ei], w);
            }
        }
        #pragma unroll 4
        for (int c = 0; c < 8; c++) {    // st region, k chunks 16..23
            float4 xv[4];
            #pragma unroll
            for (int ei = 0; ei < 4; ei++) xv[ei] = st4[nn[ei] * 8 + c];
            #pragma unroll
            for (int cj = 0; cj < 4; cj++) {
                float4 w = w1[(jg + 32 * cj) * 25 + (16 + c)];
                #pragma unroll
                for (int ei = 0; ei < 4; ei++) acc[ei][cj] += dot4(xv[ei], w);
            }
        }
        #pragma unroll
        for (int cj = 0; cj < 4; cj++) {
            float b = sb1[jg + 32 * cj];
            #pragma unroll
            for (int ei = 0; ei < 4; ei++)
                hbuf[(eg * 4 + ei) * H_STRIDE + jg + 32 * cj] = fmaxf(acc[ei][cj] + b, 0.f);
        }
        __syncthreads();

        // -------- layer 2 + residual + store --------
        float acc2[2][4];
        #pragma unroll
        for (int a = 0; a < 2; a++)
            #pragma unroll
            for (int b = 0; b < 4; b++) acc2[a][b] = 0.f;

        const int e30 = eg3 * 2;
        #pragma unroll 4
        for (int c = 0; c < 32; c++) {
            float4 hv[2];
            #pragma unroll
            for (int ei = 0; ei < 2; ei++) hv[ei] = h4[(e30 + ei) * 33 + c];
            #pragma unroll
            for (int r = 0; r < 4; r++) {
                float4 w = w2[(d4 * 4 + r) * 33 + c];
                #pragma unroll
                for (int ei = 0; ei < 2; ei++) acc2[ei][r] += dot4(hv[ei], w);
            }
        }
        #pragma unroll
        for (int ei = 0; ei < 2; ei++) {
            int n = nbase + e30 + ei;
            if (n < N_NODES_C) {
                float4 base = nf4[n * 16 + d4];
                float4 o;
                o.x = base.x + acc2[ei][0] + sb2[d4 * 4 + 0];
                o.y = base.y + acc2[ei][1] + sb2[d4 * 4 + 1];
                o.z = base.z + acc2[ei][2] + sb2[d4 * 4 + 2];
                o.w = base.w + acc2[ei][3] + sb2[d4 * 4 + 3];
                out4[n * 16 + d4] = o;
            }
        }
    }
}

extern "C" void kernel_launch(void* const* d_in, const int* in_sizes, int n_in,
                              void* d_out, int out_size)
{
    const float* nf  = (const float*)d_in[0];   // node_features [50000,64]
    const float* ef  = (const float*)d_in[1];   // edge_features [800000,32]
    const float* stx = (const float*)d_in[2];   // spacetime    [50000,32]
    const float* mW1 = (const float*)d_in[3];
    const float* mb1 = (const float*)d_in[4];
    const float* mW2 = (const float*)d_in[5];
    const float* mb2 = (const float*)d_in[6];
    const float* mW3 = (const float*)d_in[7];
    const float* mb3 = (const float*)d_in[8];
    const float* uW1 = (const float*)d_in[9];
    const float* ub1 = (const float*)d_in[10];
    const float* uW2 = (const float*)d_in[11];
    const float* ub2 = (const float*)d_in[12];
    const int*  eidx = (const int*)d_in[13];    // edge_indices [800000,2] int32

    float* out_node = (float*)d_out;                                  // (nf + upd)
    float* agg      = out_node + (size_t)N_NODES_C * NODE_D_C;        // aggregated

    cudaFuncSetAttribute(edge_mlp_kernel,
                         cudaFuncAttributeMaxDynamicSharedMemorySize, EDGE_SMEM_BYTES);
    cudaFuncSetAttribute(node_update_kernel,
                         cudaFuncAttributeMaxDynamicSharedMemorySize, NODE_SMEM_BYTES);

    int dev = 0;
    cudaGetDevice(&dev);
    int sms = 148;
    cudaDeviceGetAttribute(&sms, cudaDevAttrMultiProcessorCount, dev);

    // zero the aggregation half, then edge path (atomic scatter), then node path
    cudaMemsetAsync(agg, 0, (size_t)N_NODES_C * NODE_D_C * sizeof(float));
    edge_mlp_kernel<<<sms, TPB, EDGE_SMEM_BYTES>>>(nf, ef, stx, mW1, mb1, mW2, mb2,
                                                   mW3, mb3, eidx, agg);
    node_update_kernel<<<2 * sms, TPB, NODE_SMEM_BYTES>>>(nf, stx, uW1, ub1, uW2, ub2,
                                                          out_node);
}

// round 2
// speedup vs baseline: 1.0640x; 1.0640x over previous
#include <cuda_runtime.h>
#include <cstdint>

#define N_NODES_C 50000
#define N_EDGES_C 800000
#define NODE_D_C  64

#define TPB 256
#define TILE_E 32
#define TILE_N 32
#define N_TILES_E (N_EDGES_C / TILE_E)                     // 25000 exact
#define N_TILES_N ((N_NODES_C + TILE_N - 1) / TILE_N)      // 1563

// SMEM strides (floats), padded: stride mod 32 == 4 -> conflict-free LDS.128
#define W1_STRIDE 196   // 192 + 4  (49 float4)
#define W2_STRIDE 132   // 128 + 4  (33 float4)
#define W3_STRIDE 132
#define H_STRIDE  132
#define U1_STRIDE 100   // 96 + 4   (25 float4)
#define U2_STRIDE 132

#define EDGE_SMEM_FLOATS (128*W1_STRIDE + 128*W2_STRIDE + 64*W3_STRIDE + 128 + 128 + 64 + TILE_E*H_STRIDE)
#define EDGE_SMEM_BYTES  (EDGE_SMEM_FLOATS*4 + 2*TILE_E*4)
#define NODE_SMEM_FLOATS (128*U1_STRIDE + 64*U2_STRIDE + 128 + 64 + TILE_N*H_STRIDE)
#define NODE_SMEM_BYTES  (NODE_SMEM_FLOATS*4)

typedef unsigned long long u64;

// 16B load viewed as two packed f32x2 (k-pair) operands.
struct V4 { u64 a, b; };

__device__ __forceinline__ uint32_t smem_u32(const void* p) {
    return (uint32_t)__cvta_generic_to_shared(p);
}
__device__ __forceinline__ V4 ldg4(const float* p) {
    V4 r;
    asm("ld.global.nc.v2.u64 {%0,%1},[%2];" : "=l"(r.a), "=l"(r.b) : "l"(p));
    return r;
}
__device__ __forceinline__ V4 lds4(uint32_t a) {
    V4 r;
    asm volatile("ld.shared.v2.u64 {%0,%1},[%2];" : "=l"(r.a), "=l"(r.b) : "r"(a));
    return r;
}
// packed dual FMA: acc.{lo,hi} += a.{lo,hi} * b.{lo,hi}
__device__ __forceinline__ void fma2(u64& c, u64 a, u64 b) {
    asm("fma.rn.f32x2 %0,%1,%2,%0;" : "+l"(c) : "l"(a), "l"(b));
}
__device__ __forceinline__ float hsum(u64 v) {
    float lo, hi;
    asm("mov.b64 {%0,%1},%2;" : "=f"(lo), "=f"(hi) : "l"(v));
    return lo + hi;
}

// ---------------------------------------------------------------------------
// Edge path. Per edge: msg_in = [nf[src](64), nf[dst](64), ef(32), st[src](32)]
// 3-layer MLP (192->128->128->64, relu, relu) then atomic scatter to agg[dst].
// Accumulators are f32x2 holding (even-k, odd-k) partial sums; final hsum.
// ---------------------------------------------------------------------------
__global__ __launch_bounds__(TPB, 1)
void edge_mlp_kernel(const float* __restrict__ nf,
                     const float* __restrict__ ef,
                     const float* __restrict__ stx,
                     const float* __restrict__ mW1, const float* __restrict__ mb1,
                     const float* __restrict__ mW2, const float* __restrict__ mb2,
                     const float* __restrict__ mW3, const float* __restrict__ mb3,
                     const int*   __restrict__ eidx,
                     float* __restrict__ agg)
{
    extern __shared__ float sm[];
    float* sW1t = sm;                              // [128][W1_STRIDE] Wt[j][k]=W1[k][j]
    float* sW2t = sW1t + 128 * W1_STRIDE;
    float* sW3t = sW2t + 128 * W2_STRIDE;          // [64][W3_STRIDE]
    float* sb1  = sW3t + 64 * W3_STRIDE;
    float* sb2  = sb1 + 128;
    float* sb3  = sb2 + 128;
    float* hbuf = sb3 + 64;                        // [TILE_E][H_STRIDE]
    int*   s_src = (int*)(hbuf + TILE_E * H_STRIDE);
    int*   s_dst = s_src + TILE_E;

    const int tid = threadIdx.x;

    for (int i = tid; i < 192 * 128; i += TPB) {
        int k = i >> 7, j = i & 127;
        sW1t[j * W1_STRIDE + k] = mW1[i];
    }
    for (int i = tid; i < 128 * 128; i += TPB) {
        int k = i >> 7, j = i & 127;
        sW2t[j * W2_STRIDE + k] = mW2[i];
    }
    for (int i = tid; i < 128 * 64; i += TPB) {
        int k = i >> 6, d = i & 63;
        sW3t[d * W3_STRIDE + k] = mW3[i];
    }
    if (tid < 128) { sb1[tid] = mb1[tid]; sb2[tid] = mb2[tid]; }
    if (tid < 64)  { sb3[tid] = mb3[tid]; }

    const int eg  = tid >> 5;    // 0..7  : edge group, layers 1-2
    const int jg  = tid & 31;    // 0..31 : hidden lane
    const int d4  = tid & 15;    // 0..15 : out float4 index, layer 3
    const int eg3 = tid >> 4;    // 0..15 : edge group, layer 3

    // byte bases for LDS
    const uint32_t w1b = smem_u32(sW1t);
    const uint32_t w2b = smem_u32(sW2t);
    const uint32_t w3b = smem_u32(sW3t);
    const uint32_t hb  = smem_u32(hbuf);

    for (int tile = blockIdx.x; tile < N_TILES_E; tile += gridDim.x) {
        __syncthreads();
        if (tid < TILE_E) {
            int2 se = ((const int2*)eidx)[tile * TILE_E + tid];
            s_src[tid] = se.x;
            s_dst[tid] = se.y;
        }
        __syncthreads();

        const int e0 = eg * 4;
        int srcs[4], dsts[4];
        #pragma unroll
        for (int ei = 0; ei < 4; ei++) {
            srcs[ei] = s_src[e0 + ei];
            dsts[ei] = s_dst[e0 + ei];
        }

        // ---------------- layer 1 ----------------
        u64 acc[4][4];
        #pragma unroll
        for (int a = 0; a < 4; a++)
            #pragma unroll
            for (int b = 0; b < 4; b++) acc[a][b] = 0ull;

        // region 1: nf[src], k-chunks 0..15
        #pragma unroll 4
        for (int c = 0; c < 16; c++) {
            V4 xv[4];
            #pragma unroll
            for (int ei = 0; ei < 4; ei++) xv[ei] = ldg4(nf + srcs[ei] * 64 + c * 4);
            #pragma unroll
            for (int cj = 0; cj < 4; cj++) {
                V4 w = lds4(w1b + ((jg + 32 * cj) * 49 + c) * 16);
                #pragma unroll
                for (int ei = 0; ei < 4; ei++) {
                    fma2(acc[ei][cj], xv[ei].a, w.a);
                    fma2(acc[ei][cj], xv[ei].b, w.b);
                }
            }
        }
        // region 2: nf[dst], k-chunks 16..31
        #pragma unroll 4
        for (int c = 0; c < 16; c++) {
            V4 xv[4];
            #pragma unroll
            for (int ei = 0; ei < 4; ei++) xv[ei] = ldg4(nf + dsts[ei] * 64 + c * 4);
            #pragma unroll
            for (int cj = 0; cj < 4; cj++) {
                V4 w = lds4(w1b + ((jg + 32 * cj) * 49 + (16 + c)) * 16);
                #pragma unroll
                for (int ei = 0; ei < 4; ei++) {
                    fma2(acc[ei][cj], xv[ei].a, w.a);
                    fma2(acc[ei][cj], xv[ei].b, w.b);
                }
            }
        }
        // region 3: ef[e], k-chunks 32..39
        #pragma unroll 4
        for (int c = 0; c < 8; c++) {
            V4 xv[4];
            #pragma unroll
            for (int ei = 0; ei < 4; ei++)
                xv[ei] = ldg4(ef + (tile * TILE_E + e0 + ei) * 32 + c * 4);
            #pragma unroll
            for (int cj = 0; cj < 4; cj++) {
                V4 w = lds4(w1b + ((jg + 32 * cj) * 49 + (32 + c)) * 16);
                #pragma unroll
                for (int ei = 0; ei < 4; ei++) {
                    fma2(acc[ei][cj], xv[ei].a, w.a);
                    fma2(acc[ei][cj], xv[ei].b, w.b);
                }
            }
        }
        // region 4: st[src], k-chunks 40..47
        #pragma unroll 4
        for (int c = 0; c < 8; c++) {
            V4 xv[4];
            #pragma unroll
            for (int ei = 0; ei < 4; ei++) xv[ei] = ldg4(stx + srcs[ei] * 32 + c * 4);
            #pragma unroll
            for (int cj = 0; cj < 4; cj++) {
                V4 w = lds4(w1b + ((jg + 32 * cj) * 49 + (40 + c)) * 16);
                #pragma unroll
                for (int ei = 0; ei < 4; ei++) {
                    fma2(acc[ei][cj], xv[ei].a, w.a);
                    fma2(acc[ei][cj], xv[ei].b, w.b);
                }
            }
        }
        #pragma unroll
        for (int cj = 0; cj < 4; cj++) {
            float b = sb1[jg + 32 * cj];
            #pragma unroll
            for (int ei = 0; ei < 4; ei++)
                hbuf[(e0 + ei) * H_STRIDE + jg + 32 * cj] = fmaxf(hsum(acc[ei][cj]) + b, 0.f);
        }
        __syncthreads();

        // ---------------- layer 2 ----------------
        u64 acc2[4][4];
        #pragma unroll
        for (int a = 0; a < 4; a++)
            #pragma unroll
            for (int b = 0; b < 4; b++) acc2[a][b] = 0ull;

        #pragma unroll 4
        for (int c = 0; c < 32; c++) {
            V4 xv[4];
            #pragma unroll
            for (int ei = 0; ei < 4; ei++)
                xv[ei] = lds4(hb + ((e0 + ei) * H_STRIDE + c * 4) * 4);
            #pragma unroll
            for (int cj = 0; cj < 4; cj++) {
                V4 w = lds4(w2b + ((jg + 32 * cj) * 33 + c) * 16);
                #pragma unroll
                for (int ei = 0; ei < 4; ei++) {
                    fma2(acc2[ei][cj], xv[ei].a, w.a);
                    fma2(acc2[ei][cj], xv[ei].b, w.b);
                }
            }
        }
        __syncthreads();   // all reads of h1 done before overwrite
        #pragma unroll
        for (int cj = 0; cj < 4; cj++) {
            float b = sb2[jg + 32 * cj];
            #pragma unroll
            for (int ei = 0; ei < 4; ei++)
                hbuf[(e0 + ei) * H_STRIDE + jg + 32 * cj] = fmaxf(hsum(acc2[ei][cj]) + b, 0.f);
        }
        __syncthreads();

        // ------------- layer 3 + scatter -------------
        u64 acc3[2][4];
        #pragma unroll
        for (int a = 0; a < 2; a++)
            #pragma unroll
            for (int b = 0; b < 4; b++) acc3[a][b] = 0ull;

        const int e30 = eg3 * 2;
        #pragma unroll 4
        for (int c = 0; c < 32; c++) {
            V4 hv[2];
            #pragma unroll
            for (int ei = 0; ei < 2; ei++)
                hv[ei] = lds4(hb + ((e30 + ei) * H_STRIDE + c * 4) * 4);
            #pragma unroll
            for (int r = 0; r < 4; r++) {
                V4 w = lds4(w3b + ((d4 * 4 + r) * 33 + c) * 16);
                #pragma unroll
                for (int ei = 0; ei < 2; ei++) {
                    fma2(acc3[ei][r], hv[ei].a, w.a);
                    fma2(acc3[ei][r], hv[ei].b, w.b);
                }
            }
        }
        #pragma unroll
        for (int ei = 0; ei < 2; ei++) {
            float4 v;
            v.x = hsum(acc3[ei][0]) + sb3[d4 * 4 + 0];
            v.y = hsum(acc3[ei][1]) + sb3[d4 * 4 + 1];
            v.z = hsum(acc3[ei][2]) + sb3[d4 * 4 + 2];
            v.w = hsum(acc3[ei][3]) + sb3[d4 * 4 + 3];
            int dn = s_dst[e30 + ei];
            atomicAdd(((float4*)(agg + (size_t)dn * NODE_D_C)) + d4, v);
        }
    }
}

// ---------------------------------------------------------------------------
// Node path: out = nf + relu([nf, st] @ uW1 + ub1) @ uW2 + ub2
// ---------------------------------------------------------------------------
__global__ __launch_bounds__(TPB, 2)
void node_update_kernel(const float* __restrict__ nf,
                        const float* __restrict__ stx,
                        const float* __restrict__ uW1, const float* __restrict__ ub1,
                        const float* __restrict__ uW2, const float* __restrict__ ub2,
                        float* __restrict__ out_node)
{
    extern __shared__ float sm[];
    float* sU1t = sm;                          // [128][U1_STRIDE]
    float* sU2t = sU1t + 128 * U1_STRIDE;      // [64][U2_STRIDE]
    float* sb1  = sU2t + 64 * U2_STRIDE;
    float* sb2  = sb1 + 128;
    float* hbuf = sb2 + 64;                    // [TILE_N][H_STRIDE]

    const int tid = threadIdx.x;
    for (int i = tid; i < 96 * 128; i += TPB) {
        int k = i >> 7, j = i & 127;
        sU1t[j * U1_STRIDE + k] = uW1[i];
    }
    for (int i = tid; i < 128 * 64; i += TPB) {
        int k = i >> 6, d = i & 63;
        sU2t[d * U2_STRIDE + k] = uW2[i];
    }
    if (tid < 128) sb1[tid] = ub1[tid];
    if (tid < 64)  sb2[tid] = ub2[tid];

    const int eg  = tid >> 5;
    const int jg  = tid & 31;
    const int d4  = tid & 15;
    const int eg3 = tid >> 4;

    const uint32_t w1b = smem_u32(sU1t);
    const uint32_t w2b = smem_u32(sU2t);
    const uint32_t hb  = smem_u32(hbuf);

    const float4* nf4 = (const float4*)nf;
    float4* out4 = (float4*)out_node;

    for (int tile = blockIdx.x; tile < N_TILES_N; tile += gridDim.x) {
        __syncthreads();
        const int nbase = tile * TILE_N;

        int nn[4];
        #pragma unroll
        for (int ei = 0; ei < 4; ei++) {
            int n = nbase + eg * 4 + ei;
            nn[ei] = (n < N_NODES_C) ? n : (N_NODES_C - 1);
        }
        u64 acc[4][4];
        #pragma unroll
        for (int a = 0; a < 4; a++)
            #pragma unroll
            for (int b = 0; b < 4; b++) acc[a][b] = 0ull;

        #pragma unroll 4
        for (int c = 0; c < 16; c++) {   // nf region
            V4 xv[4];
            #pragma unroll
            for (int ei = 0; ei < 4; ei++) xv[ei] = ldg4(nf + nn[ei] * 64 + c * 4);
            #pragma unroll
            for (int cj = 0; cj < 4; cj++) {
                V4 w = lds4(w1b + ((jg + 32 * cj) * 25 + c) * 16);
                #pragma unroll
                for (int ei = 0; ei < 4; ei++) {
                    fma2(acc[ei][cj], xv[ei].a, w.a);
                    fma2(acc[ei][cj], xv[ei].b, w.b);
                }
            }
        }
        #pragma unroll 4
        for (int c = 0; c < 8; c++) {    // st region
            V4 xv[4];
            #pragma unroll
            for (int ei = 0; ei < 4; ei++) xv[ei] = ldg4(stx + nn[ei] * 32 + c * 4);
            #pragma unroll
            for (int cj = 0; cj < 4; cj++) {
                V4 w = lds4(w1b + ((jg + 32 * cj) * 25 + (16 + c)) * 16);
                #pragma unroll
                for (int ei = 0; ei < 4; ei++) {
                    fma2(acc[ei][cj], xv[ei].a, w.a);
                    fma2(acc[ei][cj], xv[ei].b, w.b);
                }
            }
        }
        #pragma unroll
        for (int cj = 0; cj < 4; cj++) {
            float b = sb1[jg + 32 * cj];
            #pragma unroll
            for (int ei = 0; ei < 4; ei++)
                hbuf[(eg * 4 + ei) * H_STRIDE + jg + 32 * cj] = fmaxf(hsum(acc[ei][cj]) + b, 0.f);
        }
        __syncthreads();

        u64 acc2[2][4];
        #pragma unroll
        for (int a = 0; a < 2; a++)
            #pragma unroll
            for (int b = 0; b < 4; b++) acc2[a][b] = 0ull;

        const int e30 = eg3 * 2;
        #pragma unroll 4
        for (int c = 0; c < 32; c++) {
            V4 hv[2];
            #pragma unroll
            for (int ei = 0; ei < 2; ei++)
                hv[ei] = lds4(hb + ((e30 + ei) * H_STRIDE + c * 4) * 4);
            #pragma unroll
            for (int r = 0; r < 4; r++) {
                V4 w = lds4(w2b + ((d4 * 4 + r) * 33 + c) * 16);
                #pragma unroll
                for (int ei = 0; ei < 2; ei++) {
                    fma2(acc2[ei][r], hv[ei].a, w.a);
                    fma2(acc2[ei][r], hv[ei].b, w.b);
                }
            }
        }
        #pragma unroll
        for (int ei = 0; ei < 2; ei++) {
            int n = nbase + e30 + ei;
            if (n < N_NODES_C) {
                float4 base = nf4[n * 16 + d4];
                float4 o;
                o.x = base.x + hsum(acc2[ei][0]) + sb2[d4 * 4 + 0];
                o.y = base.y + hsum(acc2[ei][1]) + sb2[d4 * 4 + 1];
                o.z = base.z + hsum(acc2[ei][2]) + sb2[d4 * 4 + 2];
                o.w = base.w + hsum(acc2[ei][3]) + sb2[d4 * 4 + 3];
                out4[n * 16 + d4] = o;
            }
        }
    }
}

extern "C" void kernel_launch(void* const* d_in, const int* in_sizes, int n_in,
                              void* d_out, int out_size)
{
    const float* nf  = (const float*)d_in[0];
    const float* ef  = (const float*)d_in[1];
    const float* stx = (const float*)d_in[2];
    const float* mW1 = (const float*)d_in[3];
    const float* mb1 = (const float*)d_in[4];
    const float* mW2 = (const float*)d_in[5];
    const float* mb2 = (const float*)d_in[6];
    const float* mW3 = (const float*)d_in[7];
    const float* mb3 = (const float*)d_in[8];
    const float* uW1 = (const float*)d_in[9];
    const float* ub1 = (const float*)d_in[10];
    const float* uW2 = (const float*)d_in[11];
    const float* ub2 = (const float*)d_in[12];
    const int*  eidx = (const int*)d_in[13];

    float* out_node = (float*)d_out;
    float* agg      = out_node + (size_t)N_NODES_C * NODE_D_C;

    cudaFuncSetAttribute(edge_mlp_kernel,
                         cudaFuncAttributeMaxDynamicSharedMemorySize, EDGE_SMEM_BYTES);
    cudaFuncSetAttribute(node_update_kernel,
                         cudaFuncAttributeMaxDynamicSharedMemorySize, NODE_SMEM_BYTES);

    int dev = 0;
    cudaGetDevice(&dev);
    int sms = 148;
    cudaDeviceGetAttribute(&sms, cudaDevAttrMultiProcessorCount, dev);

    cudaMemsetAsync(agg, 0, (size_t)N_NODES_C * NODE_D_C * sizeof(float));
    edge_mlp_kernel<<<sms, TPB, EDGE_SMEM_BYTES>>>(nf, ef, stx, mW1, mb1, mW2, mb2,
                                                   mW3, mb3, eidx, agg);
    node_update_kernel<<<2 * sms, TPB, NODE_SMEM_BYTES>>>(nf, stx, uW1, ub1, uW2, ub2,
                                                          out_node);
}

// round 3
// speedup vs baseline: 1.6637x; 1.5636x over previous
#include <cuda_runtime.h>
#include <cstdint>

#define N_NODES_C 50000
#define N_EDGES_C 800000
#define NODE_D_C  64

#define TPB 512
#define TILE_E 64
#define N_TILES_E (N_EDGES_C / TILE_E)                     // 12500 exact

#define NTPB 256
#define TILE_N 32
#define N_TILES_N ((N_NODES_C + TILE_N - 1) / TILE_N)      // 1563

// ---- edge kernel smem (floats), chunk-blocked weights, no padding ----
// sW1: [48 chunks][128 j] float4   (chunk c holds k = 4c..4c+3, transposed pack)
// sW2: [32][128] float4
// sW3: [32][64]  float4
// hbuf: [64][128] floats (reads are warp-uniform broadcasts; writes within-row)
#define EDGE_SMEM_FLOATS (48*128*4 + 32*128*4 + 32*64*4 + 128 + 128 + 64 + 64*128)
#define EDGE_SMEM_BYTES  (EDGE_SMEM_FLOATS*4 + 2*TILE_E*4)   // 231,168 B

// ---- node kernel smem (unchanged from R2, padded row-major) ----
#define U1_STRIDE 100
#define U2_STRIDE 132
#define H_STRIDE_N 132
#define NODE_SMEM_FLOATS (128*U1_STRIDE + 64*U2_STRIDE + 128 + 64 + TILE_N*H_STRIDE_N)
#define NODE_SMEM_BYTES  (NODE_SMEM_FLOATS*4)

typedef unsigned long long u64;
struct V4 { u64 a, b; };

__device__ __forceinline__ uint32_t smem_u32(const void* p) {
    return (uint32_t)__cvta_generic_to_shared(p);
}
__device__ __forceinline__ V4 ldg4(const float* p) {
    V4 r;
    asm("ld.global.nc.v2.u64 {%0,%1},[%2];" : "=l"(r.a), "=l"(r.b) : "l"(p));
    return r;
}
__device__ __forceinline__ V4 lds4(uint32_t a) {
    V4 r;
    asm volatile("ld.shared.v2.u64 {%0,%1},[%2];" : "=l"(r.a), "=l"(r.b) : "r"(a));
    return r;
}
__device__ __forceinline__ void fma2(u64& c, u64 a, u64 b) {
    asm("fma.rn.f32x2 %0,%1,%2,%0;" : "+l"(c) : "l"(a), "l"(b));
}
__device__ __forceinline__ float hsum(u64 v) {
    float lo, hi;
    asm("mov.b64 {%0,%1},%2;" : "=f"(lo), "=f"(hi) : "l"(v));
    return lo + hi;
}

// ---------------------------------------------------------------------------
// Edge path. 64-edge tiles, 16 warps. Warp w owns edges w*4..w*4+3.
// Layers 1-2: per-thread microtile 4 edges x 4 hidden (j = lane + 32*cj).
// Layer 3: lane owns outputs {lane, lane+32}; m staged in smem; float4 atomics.
// ---------------------------------------------------------------------------
__global__ __launch_bounds__(TPB, 1)
void edge_mlp_kernel(const float* __restrict__ nf,
                     const float* __restrict__ ef,
                     const float* __restrict__ stx,
                     const float* __restrict__ mW1, const float* __restrict__ mb1,
                     const float* __restrict__ mW2, const float* __restrict__ mb2,
                     const float* __restrict__ mW3, const float* __restrict__ mb3,
                     const int*   __restrict__ eidx,
                     float* __restrict__ agg)
{
    extern __shared__ float sm[];
    float* sW1 = sm;                         // 48*128*4 = 24576 floats
    float* sW2 = sW1 + 48 * 128 * 4;         // 32*128*4 = 16384
    float* sW3 = sW2 + 32 * 128 * 4;         // 32*64*4  =  8192
    float* sb1 = sW3 + 32 * 64 * 4;          // 128
    float* sb2 = sb1 + 128;                  // 128
    float* sb3 = sb2 + 128;                  // 64
    float* hbuf = sb3 + 64;                  // [64][128]
    int*   s_src = (int*)(hbuf + 64 * 128);
    int*   s_dst = s_src + TILE_E;

    const int tid = threadIdx.x;

    // chunk-blocked transposed weight load: sW[(c*J + j)*4 + t] = W[(4c+t)*J + j]
    for (int i = tid; i < 192 * 128; i += TPB) {
        int k = i >> 7, j = i & 127;
        sW1[(((k >> 2) << 7) + j) * 4 + (k & 3)] = mW1[i];
    }
    for (int i = tid; i < 128 * 128; i += TPB) {
        int k = i >> 7, j = i & 127;
        sW2[(((k >> 2) << 7) + j) * 4 + (k & 3)] = mW2[i];
    }
    for (int i = tid; i < 128 * 64; i += TPB) {
        int k = i >> 6, j = i & 63;
        sW3[(((k >> 2) << 6) + j) * 4 + (k & 3)] = mW3[i];
    }
    if (tid < 128) { sb1[tid] = mb1[tid]; sb2[tid] = mb2[tid]; }
    if (tid < 64)  { sb3[tid] = mb3[tid]; }

    const int wid = tid >> 5;    // 0..15
    const int jg  = tid & 31;    // lane

    const uint32_t w1b = smem_u32(sW1);
    const uint32_t w2b = smem_u32(sW2);
    const uint32_t w3b = smem_u32(sW3);
    const uint32_t hb  = smem_u32(hbuf);

    for (int tile = blockIdx.x; tile < N_TILES_E; tile += gridDim.x) {
        __syncthreads();   // prior tile fully done with hbuf / s_src / s_dst
        if (tid < TILE_E) {
            int2 se = ((const int2*)eidx)[tile * TILE_E + tid];
            s_src[tid] = se.x;
            s_dst[tid] = se.y;
        }
        __syncthreads();

        const int e0 = wid * 4;
        int srcs[4], dsts[4];
        #pragma unroll
        for (int ei = 0; ei < 4; ei++) {
            srcs[ei] = s_src[e0 + ei];
            dsts[ei] = s_dst[e0 + ei];
        }

        // ---------------- layer 1 (k-chunks: 0-15 nf[src], 16-31 nf[dst],
        //                            32-39 ef, 40-47 st[src]) ----------------
        u64 acc[4][4];
        #pragma unroll
        for (int a = 0; a < 4; a++)
            #pragma unroll
            for (int b = 0; b < 4; b++) acc[a][b] = 0ull;

        #pragma unroll 4
        for (int c = 0; c < 16; c++) {
            V4 xv[4];
            #pragma unroll
            for (int ei = 0; ei < 4; ei++) xv[ei] = ldg4(nf + srcs[ei] * 64 + c * 4);
            #pragma unroll
            for (int cj = 0; cj < 4; cj++) {
                V4 w = lds4(w1b + ((c << 7) + jg + 32 * cj) * 16);
                #pragma unroll
                for (int ei = 0; ei < 4; ei++) {
                    fma2(acc[ei][cj], xv[ei].a, w.a);
                    fma2(acc[ei][cj], xv[ei].b, w.b);
                }
            }
        }
        #pragma unroll 4
        for (int c = 0; c < 16; c++) {
            V4 xv[4];
            #pragma unroll
            for (int ei = 0; ei < 4; ei++) xv[ei] = ldg4(nf + dsts[ei] * 64 + c * 4);
            #pragma unroll
            for (int cj = 0; cj < 4; cj++) {
                V4 w = lds4(w1b + (((16 + c) << 7) + jg + 32 * cj) * 16);
                #pragma unroll
                for (int ei = 0; ei < 4; ei++) {
                    fma2(acc[ei][cj], xv[ei].a, w.a);
                    fma2(acc[ei][cj], xv[ei].b, w.b);
                }
            }
        }
        #pragma unroll 4
        for (int c = 0; c < 8; c++) {
            V4 xv[4];
            #pragma unroll
            for (int ei = 0; ei < 4; ei++)
                xv[ei] = ldg4(ef + (tile * TILE_E + e0 + ei) * 32 + c * 4);
            #pragma unroll
            for (int cj = 0; cj < 4; cj++) {
                V4 w = lds4(w1b + (((32 + c) << 7) + jg + 32 * cj) * 16);
                #pragma unroll
                for (int ei = 0; ei < 4; ei++) {
                    fma2(acc[ei][cj], xv[ei].a, w.a);
                    fma2(acc[ei][cj], xv[ei].b, w.b);
                }
            }
        }
        #pragma unroll 4
        for (int c = 0; c < 8; c++) {
            V4 xv[4];
            #pragma unroll
            for (int ei = 0; ei < 4; ei++) xv[ei] = ldg4(stx + srcs[ei] * 32 + c * 4);
            #pragma unroll
            for (int cj = 0; cj < 4; cj++) {
                V4 w = lds4(w1b + (((40 + c) << 7) + jg + 32 * cj) * 16);
                #pragma unroll
                for (int ei = 0; ei < 4; ei++) {
                    fma2(acc[ei][cj], xv[ei].a, w.a);
                    fma2(acc[ei][cj], xv[ei].b, w.b);
                }
            }
        }
        #pragma unroll
        for (int cj = 0; cj < 4; cj++) {
            float b = sb1[jg + 32 * cj];
            #pragma unroll
            for (int ei = 0; ei < 4; ei++)
                hbuf[(e0 + ei) * 128 + jg + 32 * cj] = fmaxf(hsum(acc[ei][cj]) + b, 0.f);
        }
        __syncthreads();

        // ---------------- layer 2 ----------------
        u64 acc2[4][4];
        #pragma unroll
        for (int a = 0; a < 4; a++)
            #pragma unroll
            for (int b = 0; b < 4; b++) acc2[a][b] = 0ull;

        #pragma unroll 4
        for (int c = 0; c < 32; c++) {
            V4 xv[4];
            #pragma unroll
            for (int ei = 0; ei < 4; ei++)
                xv[ei] = lds4(hb + ((e0 + ei) * 128 + c * 4) * 4);   // warp-uniform
            #pragma unroll
            for (int cj = 0; cj < 4; cj++) {
                V4 w = lds4(w2b + ((c << 7) + jg + 32 * cj) * 16);
                #pragma unroll
                for (int ei = 0; ei < 4; ei++) {
                    fma2(acc2[ei][cj], xv[ei].a, w.a);
                    fma2(acc2[ei][cj], xv[ei].b, w.b);
                }
            }
        }
        __syncthreads();   // all h1 reads complete before overwrite
        #pragma unroll
        for (int cj = 0; cj < 4; cj++) {
            float b = sb2[jg + 32 * cj];
            #pragma unroll
            for (int ei = 0; ei < 4; ei++)
                hbuf[(e0 + ei) * 128 + jg + 32 * cj] = fmaxf(hsum(acc2[ei][cj]) + b, 0.f);
        }
        __syncthreads();

        // ------------- layer 3: lane owns outputs {jg, jg+32} -------------
        u64 acc3[4][2];
        #pragma unroll
        for (int a = 0; a < 4; a++) { acc3[a][0] = 0ull; acc3[a][1] = 0ull; }

        #pragma unroll 4
        for (int c = 0; c < 32; c++) {
            V4 hv[4];
            #pragma unroll
            for (int ei = 0; ei < 4; ei++)
                hv[ei] = lds4(hb + ((e0 + ei) * 128 + c * 4) * 4);   // warp-uniform
            V4 w0 = lds4(w3b + ((c << 6) + jg) * 16);                 // contiguous/lane
            V4 w1v = lds4(w3b + ((c << 6) + jg + 32) * 16);
            #pragma unroll
            for (int ei = 0; ei < 4; ei++) {
                fma2(acc3[ei][0], hv[ei].a, w0.a);
                fma2(acc3[ei][0], hv[ei].b, w0.b);
                fma2(acc3[ei][1], hv[ei].a, w1v.a);
                fma2(acc3[ei][1], hv[ei].b, w1v.b);
            }
        }
        __syncthreads();   // h2 reads complete; hbuf becomes message buffer
        {
            float b0 = sb3[jg], b1 = sb3[jg + 32];
            #pragma unroll
            for (int ei = 0; ei < 4; ei++) {
                hbuf[(e0 + ei) * 128 + jg]      = hsum(acc3[ei][0]) + b0;
                hbuf[(e0 + ei) * 128 + jg + 32] = hsum(acc3[ei][1]) + b1;
            }
        }
        __syncthreads();

        // ------------- scatter: 64 edges x 16 float4, coalesced atomics ----
        #pragma unroll
        for (int it = tid; it < TILE_E * 16; it += TPB) {
            int e = it >> 4, q = it & 15;
            float4 v = *(float4*)(hbuf + e * 128 + q * 4);
            int dn = s_dst[e];
            atomicAdd(((float4*)(agg + (size_t)dn * NODE_D_C)) + q, v);
        }
    }
}

// ---------------------------------------------------------------------------
// Node path (unchanged from R2): out = nf + relu([nf,st]@uW1+ub1)@uW2+ub2
// ---------------------------------------------------------------------------
__global__ __launch_bounds__(NTPB, 2)
void node_update_kernel(const float* __restrict__ nf,
                        const float* __restrict__ stx,
                        const float* __restrict__ uW1, const float* __restrict__ ub1,
                        const float* __restrict__ uW2, const float* __restrict__ ub2,
                        float* __restrict__ out_node)
{
    extern __shared__ float sm[];
    float* sU1t = sm;
    float* sU2t = sU1t + 128 * U1_STRIDE;
    float* sb1  = sU2t + 64 * U2_STRIDE;
    float* sb2  = sb1 + 128;
    float* hbuf = sb2 + 64;

    const int tid = threadIdx.x;
    for (int i = tid; i < 96 * 128; i += NTPB) {
        int k = i >> 7, j = i & 127;
        sU1t[j * U1_STRIDE + k] = uW1[i];
    }
    for (int i = tid; i < 128 * 64; i += NTPB) {
        int k = i >> 6, d = i & 63;
        sU2t[d * U2_STRIDE + k] = uW2[i];
    }
    if (tid < 128) sb1[tid] = ub1[tid];
    if (tid < 64)  sb2[tid] = ub2[tid];

    const int eg  = tid >> 5;
    const int jg  = tid & 31;
    const int d4  = tid & 15;
    const int eg3 = tid >> 4;

    const uint32_t w1b = smem_u32(sU1t);
    const uint32_t w2b = smem_u32(sU2t);
    const uint32_t hb  = smem_u32(hbuf);

    const float4* nf4 = (const float4*)nf;
    float4* out4 = (float4*)out_node;

    for (int tile = blockIdx.x; tile < N_TILES_N; tile += gridDim.x) {
        __syncthreads();
        const int nbase = tile * TILE_N;

        int nn[4];
        #pragma unroll
        for (int ei = 0; ei < 4; ei++) {
            int n = nbase + eg * 4 + ei;
            nn[ei] = (n < N_NODES_C) ? n : (N_NODES_C - 1);
        }
        u64 acc[4][4];
        #pragma unroll
        for (int a = 0; a < 4; a++)
            #pragma unroll
            for (int b = 0; b < 4; b++) acc[a][b] = 0ull;

        #pragma unroll 4
        for (int c = 0; c < 16; c++) {
            V4 xv[4];
            #pragma unroll
            for (int ei = 0; ei < 4; ei++) xv[ei] = ldg4(nf + nn[ei] * 64 + c * 4);
            #pragma unroll
            for (int cj = 0; cj < 4; cj++) {
                V4 w = lds4(w1b + ((jg + 32 * cj) * 25 + c) * 16);
                #pragma unroll
                for (int ei = 0; ei < 4; ei++) {
                    fma2(acc[ei][cj], xv[ei].a, w.a);
                    fma2(acc[ei][cj], xv[ei].b, w.b);
                }
            }
        }
        #pragma unroll 4
        for (int c = 0; c < 8; c++) {
            V4 xv[4];
            #pragma unroll
            for (int ei = 0; ei < 4; ei++) xv[ei] = ldg4(stx + nn[ei] * 32 + c * 4);
            #pragma unroll
            for (int cj = 0; cj < 4; cj++) {
                V4 w = lds4(w1b + ((jg + 32 * cj) * 25 + (16 + c)) * 16);
                #pragma unroll
                for (int ei = 0; ei < 4; ei++) {
                    fma2(acc[ei][cj], xv[ei].a, w.a);
                    fma2(acc[ei][cj], xv[ei].b, w.b);
                }
            }
        }
        #pragma unroll
        for (int cj = 0; cj < 4; cj++) {
            float b = sb1[jg + 32 * cj];
            #pragma unroll
            for (int ei = 0; ei < 4; ei++)
                hbuf[(eg * 4 + ei) * H_STRIDE_N + jg + 32 * cj] = fmaxf(hsum(acc[ei][cj]) + b, 0.f);
        }
        __syncthreads();

        u64 acc2[2][4];
        #pragma unroll
        for (int a = 0; a < 2; a++)
            #pragma unroll
            for (int b = 0; b < 4; b++) acc2[a][b] = 0ull;

        const int e30 = eg3 * 2;
        #pragma unroll 4
        for (int c = 0; c < 32; c++) {
            V4 hv[2];
            #pragma unroll
            for (int ei = 0; ei < 2; ei++)
                hv[ei] = lds4(hb + ((e30 + ei) * H_STRIDE_N + c * 4) * 4);
            #pragma unroll
            for (int r = 0; r < 4; r++) {
                V4 w = lds4(w2b + ((d4 * 4 + r) * 33 + c) * 16);
                #pragma unroll
                for (int ei = 0; ei < 2; ei++) {
                    fma2(acc2[ei][r], hv[ei].a, w.a);
                    fma2(acc2[ei][r], hv[ei].b, w.b);
                }
            }
        }
        #pragma unroll
        for (int ei = 0; ei < 2; ei++) {
            int n = nbase + e30 + ei;
            if (n < N_NODES_C) {
                float4 base = nf4[n * 16 + d4];
                float4 o;
                o.x = base.x + hsum(acc2[ei][0]) + sb2[d4 * 4 + 0];
                o.y = base.y + hsum(acc2[ei][1]) + sb2[d4 * 4 + 1];
                o.z = base.z + hsum(acc2[ei][2]) + sb2[d4 * 4 + 2];
                o.w = base.w + hsum(acc2[ei][3]) + sb2[d4 * 4 + 3];
                out4[n * 16 + d4] = o;
            }
        }
    }
}

extern "C" void kernel_launch(void* const* d_in, const int* in_sizes, int n_in,
                              void* d_out, int out_size)
{
    const float* nf  = (const float*)d_in[0];
    const float* ef  = (const float*)d_in[1];
    const float* stx = (const float*)d_in[2];
    const float* mW1 = (const float*)d_in[3];
    const float* mb1 = (const float*)d_in[4];
    const float* mW2 = (const float*)d_in[5];
    const float* mb2 = (const float*)d_in[6];
    const float* mW3 = (const float*)d_in[7];
    const float* mb3 = (const float*)d_in[8];
    const float* uW1 = (const float*)d_in[9];
    const float* ub1 = (const float*)d_in[10];
    const float* uW2 = (const float*)d_in[11];
    const float* ub2 = (const float*)d_in[12];
    const int*  eidx = (const int*)d_in[13];

    float* out_node = (float*)d_out;
    float* agg      = out_node + (size_t)N_NODES_C * NODE_D_C;

    cudaFuncSetAttribute(edge_mlp_kernel,
                         cudaFuncAttributeMaxDynamicSharedMemorySize, EDGE_SMEM_BYTES);
    cudaFuncSetAttribute(node_update_kernel,
                         cudaFuncAttributeMaxDynamicSharedMemorySize, NODE_SMEM_BYTES);

    int dev = 0;
    cudaGetDevice(&dev);
    int sms = 148;
    cudaDeviceGetAttribute(&sms, cudaDevAttrMultiProcessorCount, dev);

    cudaMemsetAsync(agg, 0, (size_t)N_NODES_C * NODE_D_C * sizeof(float));
    edge_mlp_kernel<<<sms, TPB, EDGE_SMEM_BYTES>>>(nf, ef, stx, mW1, mb1, mW2, mb2,
                                                   mW3, mb3, eidx, agg);
    node_update_kernel<<<2 * sms, NTPB, NODE_SMEM_BYTES>>>(nf, stx, uW1, ub1, uW2, ub2,
                                                           out_node);
}

// round 4
// speedup vs baseline: 2.5435x; 1.5288x over previous
#include <cuda_runtime.h>
#include <cstdint>

#define N_NODES_C 50000
#define N_EDGES_C 800000
#define NODE_D_C  64

#define TPB 512
#define TILE_E 64
#define N_TILES_E (N_EDGES_C / TILE_E)                     // 12500 exact

#define NTPB 256
#define TILE_N 32
#define N_TILES_N ((N_NODES_C + TILE_N - 1) / TILE_N)      // 1563

// Scratch for per-node layer-1 partials (no allocation allowed -> device globals)
__device__ float g_P[(size_t)N_NODES_C * 128];   // src-part: nf@W1[0:64] + st@W1[160:192]
__device__ float g_Q[(size_t)N_NODES_C * 128];   // dst-part: nf@W1[64:128]

// ---- edge kernel smem (floats), chunk-blocked weights, no padding ----
// sW1e: [8][128][4]  (ef rows of W1: k=128..159)
// sW2:  [32][128][4]
// sW3:  [32][64][4]
#define EDGE_SMEM_FLOATS (8*128*4 + 32*128*4 + 32*64*4 + 128 + 128 + 64 + 64*128)
#define EDGE_SMEM_BYTES  (EDGE_SMEM_FLOATS*4 + 2*TILE_E*4)   // ~149 KB

// ---- P/Q precompute kernel smem ----
#define PQ_SMEM_FLOATS (24*128*4 + 16*128*4)                 // 20480 floats = 80 KB
#define PQ_SMEM_BYTES  (PQ_SMEM_FLOATS*4)

// ---- node kernel smem (unchanged, padded row-major) ----
#define U1_STRIDE 100
#define U2_STRIDE 132
#define H_STRIDE_N 132
#define NODE_SMEM_FLOATS (128*U1_STRIDE + 64*U2_STRIDE + 128 + 64 + TILE_N*H_STRIDE_N)
#define NODE_SMEM_BYTES  (NODE_SMEM_FLOATS*4)

typedef unsigned long long u64;
struct V4 { u64 a, b; };

__device__ __forceinline__ uint32_t smem_u32(const void* p) {
    return (uint32_t)__cvta_generic_to_shared(p);
}
__device__ __forceinline__ V4 ldg4(const float* p) {
    V4 r;
    asm("ld.global.nc.v2.u64 {%0,%1},[%2];" : "=l"(r.a), "=l"(r.b) : "l"(p));
    return r;
}
__device__ __forceinline__ V4 lds4(uint32_t a) {
    V4 r;
    asm volatile("ld.shared.v2.u64 {%0,%1},[%2];" : "=l"(r.a), "=l"(r.b) : "r"(a));
    return r;
}
__device__ __forceinline__ void fma2(u64& c, u64 a, u64 b) {
    asm("fma.rn.f32x2 %0,%1,%2,%0;" : "+l"(c) : "l"(a), "l"(b));
}
__device__ __forceinline__ float hsum(u64 v) {
    float lo, hi;
    asm("mov.b64 {%0,%1},%2;" : "=f"(lo), "=f"(hi) : "l"(v));
    return lo + hi;
}

// ---------------------------------------------------------------------------
// P/Q precompute: per node n,
//   P[n][j] = sum_{k<64} nf[n][k] W1[k][j] + sum_{k<32} st[n][k] W1[160+k][j]
//   Q[n][j] = sum_{k<64} nf[n][k] W1[64+k][j]
// ---------------------------------------------------------------------------
__global__ __launch_bounds__(NTPB, 2)
void pq_precompute_kernel(const float* __restrict__ nf,
                          const float* __restrict__ stx,
                          const float* __restrict__ mW1)
{
    extern __shared__ float sm[];
    float* sWp = sm;                   // [24][128][4]  (k'=0..63 -> rows 0..63; k'=64..95 -> rows 160..191)
    float* sWq = sWp + 24 * 128 * 4;   // [16][128][4]  (rows 64..127)

    const int tid = threadIdx.x;
    for (int i = tid; i < 96 * 128; i += NTPB) {
        int k = i >> 7, j = i & 127;
        int row = (k < 64) ? k : (96 + k);           // 64..95 -> 160..191
        sWp[(((k >> 2) << 7) + j) * 4 + (k & 3)] = mW1[row * 128 + j];
    }
    for (int i = tid; i < 64 * 128; i += NTPB) {
        int k = i >> 7, j = i & 127;
        sWq[(((k >> 2) << 7) + j) * 4 + (k & 3)] = mW1[(64 + k) * 128 + j];
    }
    __syncthreads();

    const int eg = tid >> 5;   // 0..7, 4 nodes each
    const int jg = tid & 31;
    const uint32_t wpb = smem_u32(sWp);
    const uint32_t wqb = smem_u32(sWq);

    for (int tile = blockIdx.x; tile < N_TILES_N; tile += gridDim.x) {
        const int nbase = tile * TILE_N;
        int nn[4];
        #pragma unroll
        for (int ei = 0; ei < 4; ei++) {
            int n = nbase + eg * 4 + ei;
            nn[ei] = (n < N_NODES_C) ? n : (N_NODES_C - 1);
        }

        u64 p[4][4], q[4][4];
        #pragma unroll
        for (int a = 0; a < 4; a++)
            #pragma unroll
            for (int b = 0; b < 4; b++) { p[a][b] = 0ull; q[a][b] = 0ull; }

        #pragma unroll 4
        for (int c = 0; c < 16; c++) {    // nf chunks feed both P and Q
            V4 xv[4];
            #pragma unroll
            for (int ei = 0; ei < 4; ei++) xv[ei] = ldg4(nf + nn[ei] * 64 + c * 4);
            #pragma unroll
            for (int cj = 0; cj < 4; cj++) {
                V4 wp = lds4(wpb + ((c << 7) + jg + 32 * cj) * 16);
                V4 wq = lds4(wqb + ((c << 7) + jg + 32 * cj) * 16);
                #pragma unroll
                for (int ei = 0; ei < 4; ei++) {
                    fma2(p[ei][cj], xv[ei].a, wp.a);
                    fma2(p[ei][cj], xv[ei].b, wp.b);
                    fma2(q[ei][cj], xv[ei].a, wq.a);
                    fma2(q[ei][cj], xv[ei].b, wq.b);
                }
            }
        }
        #pragma unroll 4
        for (int c = 0; c < 8; c++) {     // st chunks -> P only (wp chunks 16..23)
            V4 xv[4];
            #pragma unroll
            for (int ei = 0; ei < 4; ei++) xv[ei] = ldg4(stx + nn[ei] * 32 + c * 4);
            #pragma unroll
            for (int cj = 0; cj < 4; cj++) {
                V4 wp = lds4(wpb + (((16 + c) << 7) + jg + 32 * cj) * 16);
                #pragma unroll
                for (int ei = 0; ei < 4; ei++) {
                    fma2(p[ei][cj], xv[ei].a, wp.a);
                    fma2(p[ei][cj], xv[ei].b, wp.b);
                }
            }
        }
        #pragma unroll
        for (int cj = 0; cj < 4; cj++)
            #pragma unroll
            for (int ei = 0; ei < 4; ei++) {
                g_P[(size_t)nn[ei] * 128 + jg + 32 * cj] = hsum(p[ei][cj]);
                g_Q[(size_t)nn[ei] * 128 + jg + 32 * cj] = hsum(q[ei][cj]);
            }
    }
}

// ---------------------------------------------------------------------------
// Edge path. 64-edge tiles, 16 warps; warp w owns edges w*4..w*4+3.
// Layer 1: h1 = relu(P[src] + Q[dst] + ef@W1e + b1)   (K=32 GEMM + gathers)
// ---------------------------------------------------------------------------
__global__ __launch_bounds__(TPB, 1)
void edge_mlp_kernel(const float* __restrict__ ef,
                     const float* __restrict__ mW1, const float* __restrict__ mb1,
                     const float* __restrict__ mW2, const float* __restrict__ mb2,
                     const float* __restrict__ mW3, const float* __restrict__ mb3,
                     const int*   __restrict__ eidx,
                     float* __restrict__ agg)
{
    extern __shared__ float sm[];
    float* sW1e = sm;                        // [8][128][4] = 4096 floats
    float* sW2  = sW1e + 8 * 128 * 4;        // [32][128][4]
    float* sW3  = sW2 + 32 * 128 * 4;        // [32][64][4]
    float* sb1  = sW3 + 32 * 64 * 4;
    float* sb2  = sb1 + 128;
    float* sb3  = sb2 + 128;
    float* hbuf = sb3 + 64;                  // [64][128]
    int*   s_src = (int*)(hbuf + 64 * 128);
    int*   s_dst = s_src + TILE_E;

    const int tid = threadIdx.x;

    for (int i = tid; i < 32 * 128; i += TPB) {     // W1 rows 128..159 (ef part)
        int k = i >> 7, j = i & 127;
        sW1e[(((k >> 2) << 7) + j) * 4 + (k & 3)] = mW1[(128 + k) * 128 + j];
    }
    for (int i = tid; i < 128 * 128; i += TPB) {
        int k = i >> 7, j = i & 127;
        sW2[(((k >> 2) << 7) + j) * 4 + (k & 3)] = mW2[i];
    }
    for (int i = tid; i < 128 * 64; i += TPB) {
        int k = i >> 6, j = i & 63;
        sW3[(((k >> 2) << 6) + j) * 4 + (k & 3)] = mW3[i];
    }
    if (tid < 128) { sb1[tid] = mb1[tid]; sb2[tid] = mb2[tid]; }
    if (tid < 64)  { sb3[tid] = mb3[tid]; }

    const int wid = tid >> 5;
    const int jg  = tid & 31;

    const uint32_t w1b = smem_u32(sW1e);
    const uint32_t w2b = smem_u32(sW2);
    const uint32_t w3b = smem_u32(sW3);
    const uint32_t hb  = smem_u32(hbuf);

    for (int tile = blockIdx.x; tile < N_TILES_E; tile += gridDim.x) {
        __syncthreads();
        if (tid < TILE_E) {
            int2 se = ((const int2*)eidx)[tile * TILE_E + tid];
            s_src[tid] = se.x;
            s_dst[tid] = se.y;
        }
        __syncthreads();

        const int e0 = wid * 4;
        int srcs[4], dsts[4];
        #pragma unroll
        for (int ei = 0; ei < 4; ei++) {
            srcs[ei] = s_src[e0 + ei];
            dsts[ei] = s_dst[e0 + ei];
        }

        // ---- gather per-node partials (coalesced 128B lines, L2-resident) ----
        float pf[4][4], qf[4][4];
        #pragma unroll
        for (int ei = 0; ei < 4; ei++)
            #pragma unroll
            for (int cj = 0; cj < 4; cj++) {
                pf[ei][cj] = __ldg(&g_P[(size_t)srcs[ei] * 128 + jg + 32 * cj]);
                qf[ei][cj] = __ldg(&g_Q[(size_t)dsts[ei] * 128 + jg + 32 * cj]);
            }

        // ---- layer 1: ef @ W1e (K=32) ----
        u64 acc[4][4];
        #pragma unroll
        for (int a = 0; a < 4; a++)
            #pragma unroll
            for (int b = 0; b < 4; b++) acc[a][b] = 0ull;

        #pragma unroll 4
        for (int c = 0; c < 8; c++) {
            V4 xv[4];
            #pragma unroll
            for (int ei = 0; ei < 4; ei++)
                xv[ei] = ldg4(ef + (tile * TILE_E + e0 + ei) * 32 + c * 4);
            #pragma unroll
            for (int cj = 0; cj < 4; cj++) {
                V4 w = lds4(w1b + ((c << 7) + jg + 32 * cj) * 16);
                #pragma unroll
                for (int ei = 0; ei < 4; ei++) {
                    fma2(acc[ei][cj], xv[ei].a, w.a);
                    fma2(acc[ei][cj], xv[ei].b, w.b);
                }
            }
        }
        #pragma unroll
        for (int cj = 0; cj < 4; cj++) {
            float b = sb1[jg + 32 * cj];
            #pragma unroll
            for (int ei = 0; ei < 4; ei++)
                hbuf[(e0 + ei) * 128 + jg + 32 * cj] =
                    fmaxf(hsum(acc[ei][cj]) + pf[ei][cj] + qf[ei][cj] + b, 0.f);
        }
        __syncthreads();

        // ---------------- layer 2 ----------------
        u64 acc2[4][4];
        #pragma unroll
        for (int a = 0; a < 4; a++)
            #pragma unroll
            for (int b = 0; b < 4; b++) acc2[a][b] = 0ull;

        #pragma unroll 4
        for (int c = 0; c < 32; c++) {
            V4 xv[4];
            #pragma unroll
            for (int ei = 0; ei < 4; ei++)
                xv[ei] = lds4(hb + ((e0 + ei) * 128 + c * 4) * 4);   // warp-uniform
            #pragma unroll
            for (int cj = 0; cj < 4; cj++) {
                V4 w = lds4(w2b + ((c << 7) + jg + 32 * cj) * 16);
                #pragma unroll
                for (int ei = 0; ei < 4; ei++) {
                    fma2(acc2[ei][cj], xv[ei].a, w.a);
                    fma2(acc2[ei][cj], xv[ei].b, w.b);
                }
            }
        }
        __syncthreads();
        #pragma unroll
        for (int cj = 0; cj < 4; cj++) {
            float b = sb2[jg + 32 * cj];
            #pragma unroll
            for (int ei = 0; ei < 4; ei++)
                hbuf[(e0 + ei) * 128 + jg + 32 * cj] = fmaxf(hsum(acc2[ei][cj]) + b, 0.f);
        }
        __syncthreads();

        // ------------- layer 3: lane owns outputs {jg, jg+32} -------------
        u64 acc3[4][2];
        #pragma unroll
        for (int a = 0; a < 4; a++) { acc3[a][0] = 0ull; acc3[a][1] = 0ull; }

        #pragma unroll 4
        for (int c = 0; c < 32; c++) {
            V4 hv[4];
            #pragma unroll
            for (int ei = 0; ei < 4; ei++)
                hv[ei] = lds4(hb + ((e0 + ei) * 128 + c * 4) * 4);
            V4 w0  = lds4(w3b + ((c << 6) + jg) * 16);
            V4 w1v = lds4(w3b + ((c << 6) + jg + 32) * 16);
            #pragma unroll
            for (int ei = 0; ei < 4; ei++) {
                fma2(acc3[ei][0], hv[ei].a, w0.a);
                fma2(acc3[ei][0], hv[ei].b, w0.b);
                fma2(acc3[ei][1], hv[ei].a, w1v.a);
                fma2(acc3[ei][1], hv[ei].b, w1v.b);
            }
        }
        __syncthreads();
        {
            float b0 = sb3[jg], b1 = sb3[jg + 32];
            #pragma unroll
            for (int ei = 0; ei < 4; ei++) {
                hbuf[(e0 + ei) * 128 + jg]      = hsum(acc3[ei][0]) + b0;
                hbuf[(e0 + ei) * 128 + jg + 32] = hsum(acc3[ei][1]) + b1;
            }
        }
        __syncthreads();

        // ------------- scatter: coalesced float4 atomics -------------
        #pragma unroll
        for (int it = tid; it < TILE_E * 16; it += TPB) {
            int e = it >> 4, q = it & 15;
            float4 v = *(float4*)(hbuf + e * 128 + q * 4);
            int dn = s_dst[e];
            atomicAdd(((float4*)(agg + (size_t)dn * NODE_D_C)) + q, v);
        }
    }
}

// ---------------------------------------------------------------------------
// Node path: out = nf + relu([nf,st]@uW1+ub1)@uW2+ub2   (unchanged, proven)
// ---------------------------------------------------------------------------
__global__ __launch_bounds__(NTPB, 2)
void node_update_kernel(const float* __restrict__ nf,
                        const float* __restrict__ stx,
                        const float* __restrict__ uW1, const float* __restrict__ ub1,
                        const float* __restrict__ uW2, const float* __restrict__ ub2,
                        float* __restrict__ out_node)
{
    extern __shared__ float sm[];
    float* sU1t = sm;
    float* sU2t = sU1t + 128 * U1_STRIDE;
    float* sb1  = sU2t + 64 * U2_STRIDE;
    float* sb2  = sb1 + 128;
    float* hbuf = sb2 + 64;

    const int tid = threadIdx.x;
    for (int i = tid; i < 96 * 128; i += NTPB) {
        int k = i >> 7, j = i & 127;
        sU1t[j * U1_STRIDE + k] = uW1[i];
    }
    for (int i = tid; i < 128 * 64; i += NTPB) {
        int k = i >> 6, d = i & 63;
        sU2t[d * U2_STRIDE + k] = uW2[i];
    }
    if (tid < 128) sb1[tid] = ub1[tid];
    if (tid < 64)  sb2[tid] = ub2[tid];

    const int eg  = tid >> 5;
    const int jg  = tid & 31;
    const int d4  = tid & 15;
    const int eg3 = tid >> 4;

    const uint32_t w1b = smem_u32(sU1t);
    const uint32_t w2b = smem_u32(sU2t);
    const uint32_t hb  = smem_u32(hbuf);

    const float4* nf4 = (const float4*)nf;
    float4* out4 = (float4*)out_node;

    for (int tile = blockIdx.x; tile < N_TILES_N; tile += gridDim.x) {
        __syncthreads();
        const int nbase = tile * TILE_N;

        int nn[4];
        #pragma unroll
        for (int ei = 0; ei < 4; ei++) {
            int n = nbase + eg * 4 + ei;
            nn[ei] = (n < N_NODES_C) ? n : (N_NODES_C - 1);
        }
        u64 acc[4][4];
        #pragma unroll
        for (int a = 0; a < 4; a++)
            #pragma unroll
            for (int b = 0; b < 4; b++) acc[a][b] = 0ull;

        #pragma unroll 4
        for (int c = 0; c < 16; c++) {
            V4 xv[4];
            #pragma unroll
            for (int ei = 0; ei < 4; ei++) xv[ei] = ldg4(nf + nn[ei] * 64 + c * 4);
            #pragma unroll
            for (int cj = 0; cj < 4; cj++) {
                V4 w = lds4(w1b + ((jg + 32 * cj) * 25 + c) * 16);
                #pragma unroll
                for (int ei = 0; ei < 4; ei++) {
                    fma2(acc[ei][cj], xv[ei].a, w.a);
                    fma2(acc[ei][cj], xv[ei].b, w.b);
                }
            }
        }
        #pragma unroll 4
        for (int c = 0; c < 8; c++) {
            V4 xv[4];
            #pragma unroll
            for (int ei = 0; ei < 4; ei++) xv[ei] = ldg4(stx + nn[ei] * 32 + c * 4);
            #pragma unroll
            for (int cj = 0; cj < 4; cj++) {
                V4 w = lds4(w1b + ((jg + 32 * cj) * 25 + (16 + c)) * 16);
                #pragma unroll
                for (int ei = 0; ei < 4; ei++) {
                    fma2(acc[ei][cj], xv[ei].a, w.a);
                    fma2(acc[ei][cj], xv[ei].b, w.b);
                }
            }
        }
        #pragma unroll
        for (int cj = 0; cj < 4; cj++) {
            float b = sb1[jg + 32 * cj];
            #pragma unroll
            for (int ei = 0; ei < 4; ei++)
                hbuf[(eg * 4 + ei) * H_STRIDE_N + jg + 32 * cj] = fmaxf(hsum(acc[ei][cj]) + b, 0.f);
        }
        __syncthreads();

        u64 acc2[2][4];
        #pragma unroll
        for (int a = 0; a < 2; a++)
            #pragma unroll
            for (int b = 0; b < 4; b++) acc2[a][b] = 0ull;

        const int e30 = eg3 * 2;
        #pragma unroll 4
        for (int c = 0; c < 32; c++) {
            V4 hv[2];
            #pragma unroll
            for (int ei = 0; ei < 2; ei++)
                hv[ei] = lds4(hb + ((e30 + ei) * H_STRIDE_N + c * 4) * 4);
            #pragma unroll
            for (int r = 0; r < 4; r++) {
                V4 w = lds4(w2b + ((d4 * 4 + r) * 33 + c) * 16);
                #pragma unroll
                for (int ei = 0; ei < 2; ei++) {
                    fma2(acc2[ei][r], hv[ei].a, w.a);
                    fma2(acc2[ei][r], hv[ei].b, w.b);
                }
            }
        }
        #pragma unroll
        for (int ei = 0; ei < 2; ei++) {
            int n = nbase + e30 + ei;
            if (n < N_NODES_C) {
                float4 base = nf4[n * 16 + d4];
                float4 o;
                o.x = base.x + hsum(acc2[ei][0]) + sb2[d4 * 4 + 0];
                o.y = base.y + hsum(acc2[ei][1]) + sb2[d4 * 4 + 1];
                o.z = base.z + hsum(acc2[ei][2]) + sb2[d4 * 4 + 2];
                o.w = base.w + hsum(acc2[ei][3]) + sb2[d4 * 4 + 3];
                out4[n * 16 + d4] = o;
            }
        }
    }
}

extern "C" void kernel_launch(void* const* d_in, const int* in_sizes, int n_in,
                              void* d_out, int out_size)
{
    const float* nf  = (const float*)d_in[0];
    const float* ef  = (const float*)d_in[1];
    const float* stx = (const float*)d_in[2];
    const float* mW1 = (const float*)d_in[3];
    const float* mb1 = (const float*)d_in[4];
    const float* mW2 = (const float*)d_in[5];
    const float* mb2 = (const float*)d_in[6];
    const float* mW3 = (const float*)d_in[7];
    const float* mb3 = (const float*)d_in[8];
    const float* uW1 = (const float*)d_in[9];
    const float* ub1 = (const float*)d_in[10];
    const float* uW2 = (const float*)d_in[11];
    const float* ub2 = (const float*)d_in[12];
    const int*  eidx = (const int*)d_in[13];

    float* out_node = (float*)d_out;
    float* agg      = out_node + (size_t)N_NODES_C * NODE_D_C;

    cudaFuncSetAttribute(edge_mlp_kernel,
                         cudaFuncAttributeMaxDynamicSharedMemorySize, EDGE_SMEM_BYTES);
    cudaFuncSetAttribute(pq_precompute_kernel,
                         cudaFuncAttributeMaxDynamicSharedMemorySize, PQ_SMEM_BYTES);
    cudaFuncSetAttribute(node_update_kernel,
                         cudaFuncAttributeMaxDynamicSharedMemorySize, NODE_SMEM_BYTES);

    int dev = 0;
    cudaGetDevice(&dev);
    int sms = 148;
    cudaDeviceGetAttribute(&sms, cudaDevAttrMultiProcessorCount, dev);

    cudaMemsetAsync(agg, 0, (size_t)N_NODES_C * NODE_D_C * sizeof(float));
    pq_precompute_kernel<<<2 * sms, NTPB, PQ_SMEM_BYTES>>>(nf, stx, mW1);
    edge_mlp_kernel<<<sms, TPB, EDGE_SMEM_BYTES>>>(ef, mW1, mb1, mW2, mb2,
                                                   mW3, mb3, eidx, agg);
    node_update_kernel<<<2 * sms, NTPB, NODE_SMEM_BYTES>>>(nf, stx, uW1, ub1, uW2, ub2,
                                                           out_node);
}

// round 6
// speedup vs baseline: 5.8667x; 2.3065x over previous
#include <cuda_runtime.h>
#include <cuda_bf16.h>
#include <cstdint>

#define N_NODES_C 50000
#define N_EDGES_C 800000

#define TPB 256            // 8 warps; each warp owns 16 edges of a 128-edge tile
#define TILE_E 128
#define N_TILES_E (N_EDGES_C / TILE_E)      // 6250 exact

#define NTPB 256
#define TILE_N 32
#define N_TILES_N ((N_NODES_C + TILE_N - 1) / TILE_N)

// Per-node layer-1 partials (scratch; no allocation allowed)
__device__ float g_P[(size_t)N_NODES_C * 128];   // nf@W1[0:64] + st@W1[160:192]
__device__ float g_Q[(size_t)N_NODES_C * 128];   // nf@W1[64:128]

// ---------------- edge kernel SMEM (bytes) ----------------
// Weight B-fragments, per (kc,nc,laneT): uint4 {b0h,b1h,b0l,b1l} (16B)
#define OFF_W1 0                          // kc=2, nc=16 : 2*16*32*16  = 16384
#define OFF_W2 16384                      // kc=8, nc=16 : 8*16*32*16  = 65536
#define OFF_W3 81920                      // kc=8, nc=8  : 8*8*32*16   = 32768
#define OFF_B1 114688                     // 128 f32
#define OFF_B2 115200                     // 128 f32
#define OFF_B3 115712                     // 64 f32
#define OFF_PQ 115968                     // 8 warps * 16 rows * 136 f32 = 69632
#define PQ_WARP_BYTES (16*136*4)          // 8704
#define EDGE_SMEM_BYTES (OFF_PQ + 8*PQ_WARP_BYTES)   // 185600

static __device__ __forceinline__ uint32_t smem_u32(const void* p) {
    return (uint32_t)__cvta_generic_to_shared(p);
}

// bf16 split of a float pair -> packed bf16x2 (low half = first arg / even idx)
static __device__ __forceinline__ void bsplit2(float x0, float x1,
                                               uint32_t& hi, uint32_t& lo) {
    uint32_t h;
    asm("cvt.rn.bf16x2.f32 %0, %1, %2;" : "=r"(h) : "f"(x1), "f"(x0));
    float r0 = x0 - __uint_as_float(h << 16);
    float r1 = x1 - __uint_as_float(h & 0xFFFF0000u);
    uint32_t l;
    asm("cvt.rn.bf16x2.f32 %0, %1, %2;" : "=r"(l) : "f"(r1), "f"(r0));
    hi = h; lo = l;
}

// D += A(16x16 bf16) * B(16x8 bf16), fp32 accum
static __device__ __forceinline__ void mma_bf16(float* d, const uint32_t* a,
                                                uint32_t b0, uint32_t b1) {
    asm volatile("mma.sync.aligned.m16n8k16.row.col.f32.bf16.bf16.f32 "
        "{%0,%1,%2,%3}, {%4,%5,%6,%7}, {%8,%9}, {%0,%1,%2,%3};"
        : "+f"(d[0]), "+f"(d[1]), "+f"(d[2]), "+f"(d[3])
        : "r"(a[0]), "r"(a[1]), "r"(a[2]), "r"(a[3]), "r"(b0), "r"(b1));
}

// ---------------------------------------------------------------------------
// Edge kernel. Warp-independent 16-edge pipelines, fragments chained in regs:
//   C1 = ef@W1e (K=32, mma) ; h1 = relu(C1 + PQ + b1)  [PQ staged in smem]
//   C2 = h1@W2  (K=128)     ; h2 = relu(C2 + b2)
//   C3 = h2@W3  (K=128,N=64); m  = C3 + b3 -> float4 atomic scatter
// D-frag(2j,2j+1) -> A-frag(kc=j) is an in-register identity (+bf16 split).
// ---------------------------------------------------------------------------
__global__ __launch_bounds__(TPB, 1)
void edge_mlp_kernel(const float* __restrict__ ef,
                     const float* __restrict__ mW1, const float* __restrict__ mb1,
                     const float* __restrict__ mW2, const float* __restrict__ mb2,
                     const float* __restrict__ mW3, const float* __restrict__ mb3,
                     const int*   __restrict__ eidx,
                     float* __restrict__ agg)
{
    extern __shared__ char smem[];
    const int tid  = threadIdx.x;
    const int w    = tid >> 5;
    const int lane = tid & 31;
    const int m    = lane & 3;       // col/k pair selector
    const int qrow = lane >> 2;      // fragment row r0 (r1 = r0+8)

    // ---- stage weight B-fragments (hi/lo interleaved per 16B) ----
    // W1e: rows 128..159 of mW1 [192][128]
    for (int idx = tid; idx < 2 * 16 * 32; idx += TPB) {
        int T = idx & 31, nc = (idx >> 5) & 15, kc = idx >> 9;
        int n = nc * 8 + (T >> 2);
        int k0 = kc * 16 + (T & 3) * 2;
        float w00 = mW1[(128 + k0) * 128 + n],     w01 = mW1[(128 + k0 + 1) * 128 + n];
        float w10 = mW1[(128 + k0 + 8) * 128 + n], w11 = mW1[(128 + k0 + 9) * 128 + n];
        uint32_t b0h, b0l, b1h, b1l;
        bsplit2(w00, w01, b0h, b0l);
        bsplit2(w10, w11, b1h, b1l);
        *(uint4*)(smem + OFF_W1 + idx * 16) = make_uint4(b0h, b1h, b0l, b1l);
    }
    // W2 [128][128]
    for (int idx = tid; idx < 8 * 16 * 32; idx += TPB) {
        int T = idx & 31, nc = (idx >> 5) & 15, kc = idx >> 9;
        int n = nc * 8 + (T >> 2);
        int k0 = kc * 16 + (T & 3) * 2;
        float w00 = mW2[k0 * 128 + n],       w01 = mW2[(k0 + 1) * 128 + n];
        float w10 = mW2[(k0 + 8) * 128 + n], w11 = mW2[(k0 + 9) * 128 + n];
        uint32_t b0h, b0l, b1h, b1l;
        bsplit2(w00, w01, b0h, b0l);
        bsplit2(w10, w11, b1h, b1l);
        *(uint4*)(smem + OFF_W2 + idx * 16) = make_uint4(b0h, b1h, b0l, b1l);
    }
    // W3 [128][64]
    for (int idx = tid; idx < 8 * 8 * 32; idx += TPB) {
        int T = idx & 31, nc = (idx >> 5) & 7, kc = idx >> 8;
        int n = nc * 8 + (T >> 2);
        int k0 = kc * 16 + (T & 3) * 2;
        float w00 = mW3[k0 * 64 + n],       w01 = mW3[(k0 + 1) * 64 + n];
        float w10 = mW3[(k0 + 8) * 64 + n], w11 = mW3[(k0 + 9) * 64 + n];
        uint32_t b0h, b0l, b1h, b1l;
        bsplit2(w00, w01, b0h, b0l);
        bsplit2(w10, w11, b1h, b1l);
        *(uint4*)(smem + OFF_W3 + idx * 16) = make_uint4(b0h, b1h, b0l, b1l);
    }
    float* b1s = (float*)(smem + OFF_B1);
    float* b2s = (float*)(smem + OFF_B2);
    float* b3s = (float*)(smem + OFF_B3);
    if (tid < 128) { b1s[tid] = mb1[tid]; b2s[tid] = mb2[tid]; }
    if (tid < 64)  { b3s[tid] = mb3[tid]; }
    __syncthreads();

    float* pq = (float*)(smem + OFF_PQ + w * PQ_WARP_BYTES);   // [16][136]
    const float4 bv1 = ((const float4*)b1s)[lane];             // b1 chunk for staging

    for (int tile = blockIdx.x; tile < N_TILES_E; tile += gridDim.x) {
        const int base_e = tile * TILE_E + w * 16;

        int2 se = make_int2(0, 0);
        if (lane < 16) se = ((const int2*)eidx)[base_e + lane];
        __syncwarp();    // also fences pq reuse from previous tile

        // ---- stage PQ = P[src] + Q[dst] + b1 into warp-private smem ----
        #pragma unroll 4
        for (int r = 0; r < 16; r++) {
            int sr = __shfl_sync(0xffffffffu, se.x, r);
            int dr = __shfl_sync(0xffffffffu, se.y, r);
            float4 pv = __ldg((const float4*)g_P + (size_t)sr * 32 + lane);
            float4 qv = __ldg((const float4*)g_Q + (size_t)dr * 32 + lane);
            float4 o;
            o.x = pv.x + qv.x + bv1.x; o.y = pv.y + qv.y + bv1.y;
            o.z = pv.z + qv.z + bv1.z; o.w = pv.w + qv.w + bv1.w;
            *(float4*)(pq + r * 136 + lane * 4) = o;
        }
        __syncwarp();

        // ---- A1 fragments from ef (K=32) ----
        const float* e0p = ef + (size_t)(base_e + qrow) * 32;
        const float* e1p = ef + (size_t)(base_e + qrow + 8) * 32;
        uint32_t A1h[2][4], A1l[2][4];
        {
            float2 v00 = __ldg((const float2*)(e0p + 2 * m));
            float2 v01 = __ldg((const float2*)(e0p + 2 * m + 8));
            float2 v02 = __ldg((const float2*)(e0p + 2 * m + 16));
            float2 v03 = __ldg((const float2*)(e0p + 2 * m + 24));
            float2 v10 = __ldg((const float2*)(e1p + 2 * m));
            float2 v11 = __ldg((const float2*)(e1p + 2 * m + 8));
            float2 v12 = __ldg((const float2*)(e1p + 2 * m + 16));
            float2 v13 = __ldg((const float2*)(e1p + 2 * m + 24));
            bsplit2(v00.x, v00.y, A1h[0][0], A1l[0][0]);
            bsplit2(v10.x, v10.y, A1h[0][1], A1l[0][1]);
            bsplit2(v01.x, v01.y, A1h[0][2], A1l[0][2]);
            bsplit2(v11.x, v11.y, A1h[0][3], A1l[0][3]);
            bsplit2(v02.x, v02.y, A1h[1][0], A1l[1][0]);
            bsplit2(v12.x, v12.y, A1h[1][1], A1l[1][1]);
            bsplit2(v03.x, v03.y, A1h[1][2], A1l[1][2]);
            bsplit2(v13.x, v13.y, A1h[1][3], A1l[1][3]);
        }

        // ---- L1 MMA: C1[16 edges x 128] ----
        float C1[16][4];
        #pragma unroll
        for (int nc = 0; nc < 16; nc++)
            #pragma unroll
            for (int i = 0; i < 4; i++) C1[nc][i] = 0.f;
        #pragma unroll
        for (int nc = 0; nc < 16; nc++)
            #pragma unroll
            for (int kc = 0; kc < 2; kc++) {
                uint4 bw = *(const uint4*)(smem + OFF_W1 + (((kc * 16 + nc) * 32) + lane) * 16);
                mma_bf16(C1[nc], A1h[kc], bw.x, bw.y);
                mma_bf16(C1[nc], A1h[kc], bw.z, bw.w);
                mma_bf16(C1[nc], A1l[kc], bw.x, bw.y);
            }

        // ---- h1 = relu(C1 + PQ) -> A2 fragments (in-register D->A identity) ----
        uint32_t A2h[8][4], A2l[8][4];
        #pragma unroll
        for (int j = 0; j < 8; j++) {
            float2 p00 = *(const float2*)(pq + qrow * 136 + 16 * j + 2 * m);
            float2 p10 = *(const float2*)(pq + (qrow + 8) * 136 + 16 * j + 2 * m);
            float2 p01 = *(const float2*)(pq + qrow * 136 + 16 * j + 8 + 2 * m);
            float2 p11 = *(const float2*)(pq + (qrow + 8) * 136 + 16 * j + 8 + 2 * m);
            float x00 = fmaxf(C1[2 * j][0] + p00.x, 0.f);
            float x01 = fmaxf(C1[2 * j][1] + p00.y, 0.f);
            float x10 = fmaxf(C1[2 * j][2] + p10.x, 0.f);
            float x11 = fmaxf(C1[2 * j][3] + p10.y, 0.f);
            float y00 = fmaxf(C1[2 * j + 1][0] + p01.x, 0.f);
            float y01 = fmaxf(C1[2 * j + 1][1] + p01.y, 0.f);
            float y10 = fmaxf(C1[2 * j + 1][2] + p11.x, 0.f);
            float y11 = fmaxf(C1[2 * j + 1][3] + p11.y, 0.f);
            bsplit2(x00, x01, A2h[j][0], A2l[j][0]);
            bsplit2(x10, x11, A2h[j][1], A2l[j][1]);
            bsplit2(y00, y01, A2h[j][2], A2l[j][2]);
            bsplit2(y10, y11, A2h[j][3], A2l[j][3]);
        }

        // ---- L2 MMA: C2[16 x 128] ----
        float C2[16][4];
        #pragma unroll
        for (int nc = 0; nc < 16; nc++)
            #pragma unroll
            for (int i = 0; i < 4; i++) C2[nc][i] = 0.f;
        #pragma unroll
        for (int nc = 0; nc < 16; nc++)
            #pragma unroll
            for (int kc = 0; kc < 8; kc++) {
                uint4 bw = *(const uint4*)(smem + OFF_W2 + (((kc * 16 + nc) * 32) + lane) * 16);
                mma_bf16(C2[nc], A2h[kc], bw.x, bw.y);
                mma_bf16(C2[nc], A2h[kc], bw.z, bw.w);
                mma_bf16(C2[nc], A2l[kc], bw.x, bw.y);
            }

        // ---- h2 = relu(C2 + b2) -> A3 fragments ----
        uint32_t A3h[8][4], A3l[8][4];
        #pragma unroll
        for (int j = 0; j < 8; j++) {
            float2 b20 = *(const float2*)(b2s + 16 * j + 2 * m);
            float2 b21 = *(const float2*)(b2s + 16 * j + 8 + 2 * m);
            float x00 = fmaxf(C2[2 * j][0] + b20.x, 0.f);
            float x01 = fmaxf(C2[2 * j][1] + b20.y, 0.f);
            float x10 = fmaxf(C2[2 * j][2] + b20.x, 0.f);
            float x11 = fmaxf(C2[2 * j][3] + b20.y, 0.f);
            float y00 = fmaxf(C2[2 * j + 1][0] + b21.x, 0.f);
            float y01 = fmaxf(C2[2 * j + 1][1] + b21.y, 0.f);
            float y10 = fmaxf(C2[2 * j + 1][2] + b21.x, 0.f);
            float y11 = fmaxf(C2[2 * j + 1][3] + b21.y, 0.f);
            bsplit2(x00, x01, A3h[j][0], A3l[j][0]);
            bsplit2(x10, x11, A3h[j][1], A3l[j][1]);
            bsplit2(y00, y01, A3h[j][2], A3l[j][2]);
            bsplit2(y10, y11, A3h[j][3], A3l[j][3]);
        }

        // ---- L3 MMA: C3[16 x 64] ----
        float C3[8][4];
        #pragma unroll
        for (int nc = 0; nc < 8; nc++)
            #pragma unroll
            for (int i = 0; i < 4; i++) C3[nc][i] = 0.f;
        #pragma unroll
        for (int nc = 0; nc < 8; nc++)
            #pragma unroll
            for (int kc = 0; kc < 8; kc++) {
                uint4 bw = *(const uint4*)(smem + OFF_W3 + (((kc * 8 + nc) * 32) + lane) * 16);
                mma_bf16(C3[nc], A3h[kc], bw.x, bw.y);
                mma_bf16(C3[nc], A3h[kc], bw.z, bw.w);
                mma_bf16(C3[nc], A3l[kc], bw.x, bw.y);
            }

        // ---- m = C3 + b3 -> msg smem (reuse pq region, stride 72) ----
        float* msg = pq;
        __syncwarp();
        #pragma unroll
        for (int nc = 0; nc < 8; nc++) {
            float2 b3v = *(const float2*)(b3s + 8 * nc + 2 * m);
            float2 o0, o1;
            o0.x = C3[nc][0] + b3v.x; o0.y = C3[nc][1] + b3v.y;
            o1.x = C3[nc][2] + b3v.x; o1.y = C3[nc][3] + b3v.y;
            *(float2*)(msg + qrow * 72 + 8 * nc + 2 * m) = o0;
            *(float2*)(msg + (qrow + 8) * 72 + 8 * nc + 2 * m) = o1;
        }
        __syncwarp();

        // ---- scatter: 16 edges x 16 float4 atomics ----
        #pragma unroll
        for (int it = 0; it < 8; it++) {
            int slot = it * 32 + lane;
            int e = slot >> 4, q = slot & 15;
            float4 v = *(const float4*)(msg + e * 72 + q * 4);
            int dn = __shfl_sync(0xffffffffu, se.y, e);
            atomicAdd(((float4*)(agg + (size_t)dn * 64)) + q, v);
        }
    }
}

// ===========================================================================
// SIMT fp32 helpers + pq / node kernels (unchanged from R4 — proven)
// ===========================================================================
typedef unsigned long long u64;
struct V4 { u64 a, b; };
static __device__ __forceinline__ V4 ldg4(const float* p) {
    V4 r;
    asm("ld.global.nc.v2.u64 {%0,%1},[%2];" : "=l"(r.a), "=l"(r.b) : "l"(p));
    return r;
}
static __device__ __forceinline__ V4 lds4(uint32_t a) {
    V4 r;
    asm volatile("ld.shared.v2.u64 {%0,%1},[%2];" : "=l"(r.a), "=l"(r.b) : "r"(a));
    return r;
}
static __device__ __forceinline__ void fma2(u64& c, u64 a, u64 b) {
    asm("fma.rn.f32x2 %0,%1,%2,%0;" : "+l"(c) : "l"(a), "l"(b));
}
static __device__ __forceinline__ float hsum(u64 v) {
    float lo, hi;
    asm("mov.b64 {%0,%1},%2;" : "=f"(lo), "=f"(hi) : "l"(v));
    return lo + hi;
}

#define U1_STRIDE 100
#define U2_STRIDE 132
#define H_STRIDE_N 132
#define NODE_SMEM_FLOATS (128*U1_STRIDE + 64*U2_STRIDE + 128 + 64 + TILE_N*H_STRIDE_N)
#define NODE_SMEM_BYTES  (NODE_SMEM_FLOATS*4)
#define PQ_SMEM_FLOATS (24*128*4 + 16*128*4)
#define PQ_SMEM_BYTES  (PQ_SMEM_FLOATS*4)

__global__ __launch_bounds__(NTPB, 2)
void pq_precompute_kernel(const float* __restrict__ nf,
                          const float* __restrict__ stx,
                          const float* __restrict__ mW1)
{
    extern __shared__ float sm[];
    float* sWp = sm;
    float* sWq = sWp + 24 * 128 * 4;

    const int tid = threadIdx.x;
    for (int i = tid; i < 96 * 128; i += NTPB) {
        int k = i >> 7, j = i & 127;
        int row = (k < 64) ? k : (96 + k);
        sWp[(((k >> 2) << 7) + j) * 4 + (k & 3)] = mW1[row * 128 + j];
    }
    for (int i = tid; i < 64 * 128; i += NTPB) {
        int k = i >> 7, j = i & 127;
        sWq[(((k >> 2) << 7) + j) * 4 + (k & 3)] = mW1[(64 + k) * 128 + j];
    }
    __syncthreads();

    const int eg = tid >> 5;
    const int jg = tid & 31;
    const uint32_t wpb = smem_u32(sWp);
    const uint32_t wqb = smem_u32(sWq);

    for (int tile = blockIdx.x; tile < N_TILES_N; tile += gridDim.x) {
        const int nbase = tile * TILE_N;
        int nn[4];
        #pragma unroll
        for (int ei = 0; ei < 4; ei++) {
            int n = nbase + eg * 4 + ei;
            nn[ei] = (n < N_NODES_C) ? n : (N_NODES_C - 1);
        }
        u64 p[4][4], q[4][4];
        #pragma unroll
        for (int a = 0; a < 4; a++)
            #pragma unroll
            for (int b = 0; b < 4; b++) { p[a][b] = 0ull; q[a][b] = 0ull; }

        #pragma unroll 4
        for (int c = 0; c < 16; c++) {
            V4 xv[4];
            #pragma unroll
            for (int ei = 0; ei < 4; ei++) xv[ei] = ldg4(nf + nn[ei] * 64 + c * 4);
            #pragma unroll
            for (int cj = 0; cj < 4; cj++) {
                V4 wp = lds4(wpb + ((c << 7) + jg + 32 * cj) * 16);
                V4 wq = lds4(wqb + ((c << 7) + jg + 32 * cj) * 16);
                #pragma unroll
                for (int ei = 0; ei < 4; ei++) {
                    fma2(p[ei][cj], xv[ei].a, wp.a);
                    fma2(p[ei][cj], xv[ei].b, wp.b);
                    fma2(q[ei][cj], xv[ei].a, wq.a);
                    fma2(q[ei][cj], xv[ei].b, wq.b);
                }
            }
        }
        #pragma unroll 4
        for (int c = 0; c < 8; c++) {
            V4 xv[4];
            #pragma unroll
            for (int ei = 0; ei < 4; ei++) xv[ei] = ldg4(stx + nn[ei] * 32 + c * 4);
            #pragma unroll
            for (int cj = 0; cj < 4; cj++) {
                V4 wp = lds4(wpb + (((16 + c) << 7) + jg + 32 * cj) * 16);
                #pragma unroll
                for (int ei = 0; ei < 4; ei++) {
                    fma2(p[ei][cj], xv[ei].a, wp.a);
                    fma2(p[ei][cj], xv[ei].b, wp.b);
                }
            }
        }
        #pragma unroll
        for (int cj = 0; cj < 4; cj++)
            #pragma unroll
            for (int ei = 0; ei < 4; ei++) {
                g_P[(size_t)nn[ei] * 128 + jg + 32 * cj] = hsum(p[ei][cj]);
                g_Q[(size_t)nn[ei] * 128 + jg + 32 * cj] = hsum(q[ei][cj]);
            }
    }
}

__global__ __launch_bounds__(NTPB, 2)
void node_update_kernel(const float* __restrict__ nf,
                        const float* __restrict__ stx,
                        const float* __restrict__ uW1, const float* __restrict__ ub1,
                        const float* __restrict__ uW2, const float* __restrict__ ub2,
                        float* __restrict__ out_node)
{
    extern __shared__ float sm[];
    float* sU1t = sm;
    float* sU2t = sU1t + 128 * U1_STRIDE;
    float* sb1  = sU2t + 64 * U2_STRIDE;
    float* sb2  = sb1 + 128;
    float* hbuf = sb2 + 64;

    const int tid = threadIdx.x;
    for (int i = tid; i < 96 * 128; i += NTPB) {
        int k = i >> 7, j = i & 127;
        sU1t[j * U1_STRIDE + k] = uW1[i];
    }
    for (int i = tid; i < 128 * 64; i += NTPB) {
        int k = i >> 6, d = i & 63;
        sU2t[d * U2_STRIDE + k] = uW2[i];
    }
    if (tid < 128) sb1[tid] = ub1[tid];
    if (tid < 64)  sb2[tid] = ub2[tid];

    const int eg  = tid >> 5;
    const int jg  = tid & 31;
    const int d4  = tid & 15;
    const int eg3 = tid >> 4;

    const uint32_t w1b = smem_u32(sU1t);
    const uint32_t w2b = smem_u32(sU2t);
    const uint32_t hb  = smem_u32(hbuf);

    const float4* nf4 = (const float4*)nf;
    float4* out4 = (float4*)out_node;

    for (int tile = blockIdx.x; tile < N_TILES_N; tile += gridDim.x) {
        __syncthreads();
        const int nbase = tile * TILE_N;

        int nn[4];
        #pragma unroll
        for (int ei = 0; ei < 4; ei++) {
            int n = nbase + eg * 4 + ei;
            nn[ei] = (n < N_NODES_C) ? n : (N_NODES_C - 1);
        }
        u64 acc[4][4];
        #pragma unroll
        for (int a = 0; a < 4; a++)
            #pragma unroll
            for (int b = 0; b < 4; b++) acc[a][b] = 0ull;

        #pragma unroll 4
        for (int c = 0; c < 16; c++) {
            V4 xv[4];
            #pragma unroll
            for (int ei = 0; ei < 4; ei++) xv[ei] = ldg4(nf + nn[ei] * 64 + c * 4);
            #pragma unroll
            for (int cj = 0; cj < 4; cj++) {
                V4 w = lds4(w1b + ((jg + 32 * cj) * 25 + c) * 16);
                #pragma unroll
                for (int ei = 0; ei < 4; ei++) {
                    fma2(acc[ei][cj], xv[ei].a, w.a);
                    fma2(acc[ei][cj], xv[ei].b, w.b);
                }
            }
        }
        #pragma unroll 4
        for (int c = 0; c < 8; c++) {
            V4 xv[4];
            #pragma unroll
            for (int ei = 0; ei < 4; ei++) xv[ei] = ldg4(stx + nn[ei] * 32 + c * 4);
            #pragma unroll
            for (int cj = 0; cj < 4; cj++) {
                V4 w = lds4(w1b + ((jg + 32 * cj) * 25 + (16 + c)) * 16);
                #pragma unroll
                for (int ei = 0; ei < 4; ei++) {
                    fma2(acc[ei][cj], xv[ei].a, w.a);
                    fma2(acc[ei][cj], xv[ei].b, w.b);
                }
            }
        }
        #pragma unroll
        for (int cj = 0; cj < 4; cj++) {
            float b = sb1[jg + 32 * cj];
            #pragma unroll
            for (int ei = 0; ei < 4; ei++)
                hbuf[(eg * 4 + ei) * H_STRIDE_N + jg + 32 * cj] = fmaxf(hsum(acc[ei][cj]) + b, 0.f);
        }
        __syncthreads();

        u64 acc2[2][4];
        #pragma unroll
        for (int a = 0; a < 2; a++)
            #pragma unroll
            for (int b = 0; b < 4; b++) acc2[a][b] = 0ull;

        const int e30 = eg3 * 2;
        #pragma unroll 4
        for (int c = 0; c < 32; c++) {
            V4 hv[2];
            #pragma unroll
            for (int ei = 0; ei < 2; ei++)
                hv[ei] = lds4(hb + ((e30 + ei) * H_STRIDE_N + c * 4) * 4);
            #pragma unroll
            for (int r = 0; r < 4; r++) {
                V4 w = lds4(w2b + ((d4 * 4 + r) * 33 + c) * 16);
                #pragma unroll
                for (int ei = 0; ei < 2; ei++) {
                    fma2(acc2[ei][r], hv[ei].a, w.a);
                    fma2(acc2[ei][r], hv[ei].b, w.b);
                }
            }
        }
        #pragma unroll
        for (int ei = 0; ei < 2; ei++) {
            int n = nbase + e30 + ei;
            if (n < N_NODES_C) {
                float4 base = nf4[n * 16 + d4];
                float4 o;
                o.x = base.x + hsum(acc2[ei][0]) + sb2[d4 * 4 + 0];
                o.y = base.y + hsum(acc2[ei][1]) + sb2[d4 * 4 + 1];
                o.z = base.z + hsum(acc2[ei][2]) + sb2[d4 * 4 + 2];
                o.w = base.w + hsum(acc2[ei][3]) + sb2[d4 * 4 + 3];
                out4[n * 16 + d4] = o;
            }
        }
    }
}

extern "C" void kernel_launch(void* const* d_in, const int* in_sizes, int n_in,
                              void* d_out, int out_size)
{
    const float* nf  = (const float*)d_in[0];
    const float* ef  = (const float*)d_in[1];
    const float* stx = (const float*)d_in[2];
    const float* mW1 = (const float*)d_in[3];
    const float* mb1 = (const float*)d_in[4];
    const float* mW2 = (const float*)d_in[5];
    const float* mb2 = (const float*)d_in[6];
    const float* mW3 = (const float*)d_in[7];
    const float* mb3 = (const float*)d_in[8];
    const float* uW1 = (const float*)d_in[9];
    const float* ub1 = (const float*)d_in[10];
    const float* uW2 = (const float*)d_in[11];
    const float* ub2 = (const float*)d_in[12];
    const int*  eidx = (const int*)d_in[13];

    float* out_node = (float*)d_out;
    float* agg      = out_node + (size_t)N_NODES_C * 64;

    cudaFuncSetAttribute(edge_mlp_kernel,
                         cudaFuncAttributeMaxDynamicSharedMemorySize, EDGE_SMEM_BYTES);
    cudaFuncSetAttribute(pq_precompute_kernel,
                         cudaFuncAttributeMaxDynamicSharedMemorySize, PQ_SMEM_BYTES);
    cudaFuncSetAttribute(node_update_kernel,
                         cudaFuncAttributeMaxDynamicSharedMemorySize, NODE_SMEM_BYTES);

    int dev = 0;
    cudaGetDevice(&dev);
    int sms = 148;
    cudaDeviceGetAttribute(&sms, cudaDevAttrMultiProcessorCount, dev);

    cudaMemsetAsync(agg, 0, (size_t)N_NODES_C * 64 * sizeof(float));
    pq_precompute_kernel<<<2 * sms, NTPB, PQ_SMEM_BYTES>>>(nf, stx, mW1);
    edge_mlp_kernel<<<sms, TPB, EDGE_SMEM_BYTES>>>(ef, mW1, mb1, mW2, mb2,
                                                   mW3, mb3, eidx, agg);
    node_update_kernel<<<2 * sms, NTPB, NODE_SMEM_BYTES>>>(nf, stx, uW1, ub1, uW2, ub2,
                                                           out_node);
}

// round 7
// speedup vs baseline: 7.8019x; 1.3299x over previous
#include <cuda_runtime.h>
#include <cuda_bf16.h>
#include <cstdint>

#define N_NODES_C 50000
#define N_EDGES_C 800000

#define TPB 256            // 8 warps; each warp owns 16 rows of a 128-row tile
#define TILE_E 128
#define N_TILES_E (N_EDGES_C / TILE_E)      // 6250 exact
#define N_WT_NODE (N_NODES_C / 16)          // 3125 warp-tiles exact

// Per-node layer-1 partials (scratch; no allocation allowed)
__device__ float g_P[(size_t)N_NODES_C * 128];   // nf@W1[0:64] + st@W1[160:192]
__device__ float g_Q[(size_t)N_NODES_C * 128];   // nf@W1[64:128]

// ---------------- edge kernel SMEM (bytes) ----------------
#define OFF_W1 0                          // kc=2, nc=16 : 16384
#define OFF_W2 16384                      // kc=8, nc=16 : 65536
#define OFF_W3 81920                      // kc=8, nc=8  : 32768
#define OFF_B1 114688                     // 128 f32
#define OFF_B2 115200                     // 128 f32
#define OFF_B3 115712                     // 64 f32
#define OFF_PQ 115968                     // 8 warps * 16 rows * 136 f32
#define PQ_WARP_BYTES (16*136*4)          // 8704
#define EDGE_SMEM_BYTES (OFF_PQ + 8*PQ_WARP_BYTES)   // 185600

// ---------------- fused node kernel SMEM (bytes) ----------------
#define NOFF_BP  0                        // P weights:  kc=6, nc=16 : 49152
#define NOFF_BQ  49152                    // Q weights:  kc=4, nc=16 : 32768
#define NOFF_BU1 81920                    // uW1:        kc=6, nc=16 : 49152
#define NOFF_BU2 131072                   // uW2:        kc=8, nc=8  : 32768
#define NOFF_UB1 163840                   // 128 f32
#define NOFF_UB2 164352                   // 64 f32
#define NODEF_SMEM_BYTES (164608)

static __device__ __forceinline__ uint32_t smem_u32(const void* p) {
    return (uint32_t)__cvta_generic_to_shared(p);
}

// bf16 split of a float pair -> packed bf16x2 (low half = first arg / even idx)
static __device__ __forceinline__ void bsplit2(float x0, float x1,
                                               uint32_t& hi, uint32_t& lo) {
    uint32_t h;
    asm("cvt.rn.bf16x2.f32 %0, %1, %2;" : "=r"(h) : "f"(x1), "f"(x0));
    float r0 = x0 - __uint_as_float(h << 16);
    float r1 = x1 - __uint_as_float(h & 0xFFFF0000u);
    uint32_t l;
    asm("cvt.rn.bf16x2.f32 %0, %1, %2;" : "=r"(l) : "f"(r1), "f"(r0));
    hi = h; lo = l;
}

// D += A(16x16 bf16) * B(16x8 bf16), fp32 accum
static __device__ __forceinline__ void mma_bf16(float* d, const uint32_t* a,
                                                uint32_t b0, uint32_t b1) {
    asm volatile("mma.sync.aligned.m16n8k16.row.col.f32.bf16.bf16.f32 "
        "{%0,%1,%2,%3}, {%4,%5,%6,%7}, {%8,%9}, {%0,%1,%2,%3};"
        : "+f"(d[0]), "+f"(d[1]), "+f"(d[2]), "+f"(d[3])
        : "r"(a[0]), "r"(a[1]), "r"(a[2]), "r"(a[3]), "r"(b0), "r"(b1));
}

// Stage one weight B-fragment set (hi/lo interleaved uint4) from a row-major
// W[k][n] source with arbitrary k-row remap.
#define STAGE_FRAGS(dst_off, KC, NC, KROW_EXPR, SRC_PTR, SRC_N)                 \
    for (int idx = tid; idx < (KC) * (NC) * 32; idx += TPB) {                   \
        int T = idx & 31, nc = (idx >> 5) % (NC), kc = idx / ((NC) * 32);       \
        int n = nc * 8 + (T >> 2);                                              \
        int k0 = kc * 16 + (T & 3) * 2;                                         \
        int ka = (KROW_EXPR(k0)), kb = (KROW_EXPR(k0 + 1));                     \
        int kd = (KROW_EXPR(k0 + 8)), ke = (KROW_EXPR(k0 + 9));                 \
        float w00 = (SRC_PTR)[ka * (SRC_N) + n], w01 = (SRC_PTR)[kb * (SRC_N) + n]; \
        float w10 = (SRC_PTR)[kd * (SRC_N) + n], w11 = (SRC_PTR)[ke * (SRC_N) + n]; \
        uint32_t b0h, b0l, b1h, b1l;                                            \
        bsplit2(w00, w01, b0h, b0l);                                            \
        bsplit2(w10, w11, b1h, b1l);                                            \
        *(uint4*)(smem + (dst_off) + idx * 16) = make_uint4(b0h, b1h, b0l, b1l); \
    }

#define KR_ID(k)    (k)
#define KR_W1E(k)   (128 + (k))
#define KR_P(k)     ((k) < 64 ? (k) : (k) + 96)   // nf rows 0..63; st rows 160..191
#define KR_Q(k)     (64 + (k))

// ---------------------------------------------------------------------------
// Fused node kernel: per 16-node warp-tile, shared A-frags x=[nf|st] (K=96):
//   P = nf@W1[0:64]+st@W1[160:192]; Q = nf@W1[64:128]          -> g_P,g_Q
//   h = relu(x@uW1 + ub1); out = nf + h@uW2 + ub2              -> out_node
// ---------------------------------------------------------------------------
__global__ __launch_bounds__(TPB, 1)
void node_fused_kernel(const float* __restrict__ nf,
                       const float* __restrict__ stx,
                       const float* __restrict__ mW1,
                       const float* __restrict__ uW1, const float* __restrict__ ub1,
                       const float* __restrict__ uW2, const float* __restrict__ ub2,
                       float* __restrict__ out_node)
{
    extern __shared__ char smem[];
    const int tid  = threadIdx.x;
    const int w    = tid >> 5;
    const int lane = tid & 31;
    const int m    = lane & 3;
    const int qrow = lane >> 2;

    STAGE_FRAGS(NOFF_BP,  6, 16, KR_P,  mW1, 128)
    STAGE_FRAGS(NOFF_BQ,  4, 16, KR_Q,  mW1, 128)
    STAGE_FRAGS(NOFF_BU1, 6, 16, KR_ID, uW1, 128)
    STAGE_FRAGS(NOFF_BU2, 8, 8,  KR_ID, uW2, 64)
    float* ub1s = (float*)(smem + NOFF_UB1);
    float* ub2s = (float*)(smem + NOFF_UB2);
    if (tid < 128) ub1s[tid] = ub1[tid];
    if (tid < 64)  ub2s[tid] = ub2[tid];
    __syncthreads();

    const int gw = blockIdx.x * 8 + w;
    const int gstride = gridDim.x * 8;

    for (int wt = gw; wt < N_WT_NODE; wt += gstride) {
        const int n0 = wt * 16 + qrow;
        const int n1 = n0 + 8;

        // ---- A fragments: x = [nf(64) | st(32)], kc 0..5 ----
        uint32_t xh[6][4], xl[6][4];
        #pragma unroll
        for (int kc = 0; kc < 4; kc++) {
            float2 v0  = __ldg((const float2*)(nf + (size_t)n0 * 64 + kc * 16 + 2 * m));
            float2 v1  = __ldg((const float2*)(nf + (size_t)n1 * 64 + kc * 16 + 2 * m));
            float2 v0b = __ldg((const float2*)(nf + (size_t)n0 * 64 + kc * 16 + 8 + 2 * m));
            float2 v1b = __ldg((const float2*)(nf + (size_t)n1 * 64 + kc * 16 + 8 + 2 * m));
            bsplit2(v0.x,  v0.y,  xh[kc][0], xl[kc][0]);
            bsplit2(v1.x,  v1.y,  xh[kc][1], xl[kc][1]);
            bsplit2(v0b.x, v0b.y, xh[kc][2], xl[kc][2]);
            bsplit2(v1b.x, v1b.y, xh[kc][3], xl[kc][3]);
        }
        #pragma unroll
        for (int kc = 4; kc < 6; kc++) {
            int c = (kc - 4) * 16;
            float2 v0  = __ldg((const float2*)(stx + (size_t)n0 * 32 + c + 2 * m));
            float2 v1  = __ldg((const float2*)(stx + (size_t)n1 * 32 + c + 2 * m));
            float2 v0b = __ldg((const float2*)(stx + (size_t)n0 * 32 + c + 8 + 2 * m));
            float2 v1b = __ldg((const float2*)(stx + (size_t)n1 * 32 + c + 8 + 2 * m));
            bsplit2(v0.x,  v0.y,  xh[kc][0], xl[kc][0]);
            bsplit2(v1.x,  v1.y,  xh[kc][1], xl[kc][1]);
            bsplit2(v0b.x, v0b.y, xh[kc][2], xl[kc][2]);
            bsplit2(v1b.x, v1b.y, xh[kc][3], xl[kc][3]);
        }

        // ---- P (K=96) ----
        {
            float C[16][4];
            #pragma unroll
            for (int nc = 0; nc < 16; nc++)
                #pragma unroll
                for (int i = 0; i < 4; i++) C[nc][i] = 0.f;
            #pragma unroll
            for (int nc = 0; nc < 16; nc++)
                #pragma unroll
                for (int kc = 0; kc < 6; kc++) {
                    uint4 bw = *(const uint4*)(smem + NOFF_BP + (((kc * 16 + nc) * 32) + lane) * 16);
                    mma_bf16(C[nc], xh[kc], bw.x, bw.y);
                    mma_bf16(C[nc], xh[kc], bw.z, bw.w);
                    mma_bf16(C[nc], xl[kc], bw.x, bw.y);
                }
            #pragma unroll
            for (int nc = 0; nc < 16; nc++) {
                *(float2*)(g_P + (size_t)n0 * 128 + nc * 8 + 2 * m) = make_float2(C[nc][0], C[nc][1]);
                *(float2*)(g_P + (size_t)n1 * 128 + nc * 8 + 2 * m) = make_float2(C[nc][2], C[nc][3]);
            }
        }
        // ---- Q (K=64, nf only) ----
        {
            float C[16][4];
            #pragma unroll
            for (int nc = 0; nc < 16; nc++)
                #pragma unroll
                for (int i = 0; i < 4; i++) C[nc][i] = 0.f;
            #pragma unroll
            for (int nc = 0; nc < 16; nc++)
                #pragma unroll
                for (int kc = 0; kc < 4; kc++) {
                    uint4 bw = *(const uint4*)(smem + NOFF_BQ + (((kc * 16 + nc) * 32) + lane) * 16);
                    mma_bf16(C[nc], xh[kc], bw.x, bw.y);
                    mma_bf16(C[nc], xh[kc], bw.z, bw.w);
                    mma_bf16(C[nc], xl[kc], bw.x, bw.y);
                }
            #pragma unroll
            for (int nc = 0; nc < 16; nc++) {
                *(float2*)(g_Q + (size_t)n0 * 128 + nc * 8 + 2 * m) = make_float2(C[nc][0], C[nc][1]);
                *(float2*)(g_Q + (size_t)n1 * 128 + nc * 8 + 2 * m) = make_float2(C[nc][2], C[nc][3]);
            }
        }
        // ---- h = relu(x@uW1 + ub1) -> A2 frags ----
        uint32_t A2h[8][4], A2l[8][4];
        {
            float C[16][4];
            #pragma unroll
            for (int nc = 0; nc < 16; nc++) {
                float2 b = *(const float2*)(ub1s + nc * 8 + 2 * m);
                C[nc][0] = b.x; C[nc][1] = b.y; C[nc][2] = b.x; C[nc][3] = b.y;
            }
            #pragma unroll
            for (int nc = 0; nc < 16; nc++)
                #pragma unroll
                for (int kc = 0; kc < 6; kc++) {
                    uint4 bw = *(const uint4*)(smem + NOFF_BU1 + (((kc * 16 + nc) * 32) + lane) * 16);
                    mma_bf16(C[nc], xh[kc], bw.x, bw.y);
                    mma_bf16(C[nc], xh[kc], bw.z, bw.w);
                    mma_bf16(C[nc], xl[kc], bw.x, bw.y);
                }
            #pragma unroll
            for (int j = 0; j < 8; j++) {
                float x00 = fmaxf(C[2 * j][0], 0.f),     x01 = fmaxf(C[2 * j][1], 0.f);
                float x10 = fmaxf(C[2 * j][2], 0.f),     x11 = fmaxf(C[2 * j][3], 0.f);
                float y00 = fmaxf(C[2 * j + 1][0], 0.f), y01 = fmaxf(C[2 * j + 1][1], 0.f);
                float y10 = fmaxf(C[2 * j + 1][2], 0.f), y11 = fmaxf(C[2 * j + 1][3], 0.f);
                bsplit2(x00, x01, A2h[j][0], A2l[j][0]);
                bsplit2(x10, x11, A2h[j][1], A2l[j][1]);
                bsplit2(y00, y01, A2h[j][2], A2l[j][2]);
                bsplit2(y10, y11, A2h[j][3], A2l[j][3]);
            }
        }
        // ---- out = nf + h@uW2 + ub2 ----
        {
            float C[8][4];
            #pragma unroll
            for (int nc = 0; nc < 8; nc++) {
                float2 b = *(const float2*)(ub2s + nc * 8 + 2 * m);
                C[nc][0] = b.x; C[nc][1] = b.y; C[nc][2] = b.x; C[nc][3] = b.y;
            }
            #pragma unroll
            for (int nc = 0; nc < 8; nc++)
                #pragma unroll
                for (int kc = 0; kc < 8; kc++) {
                    uint4 bw = *(const uint4*)(smem + NOFF_BU2 + (((kc * 8 + nc) * 32) + lane) * 16);
                    mma_bf16(C[nc], A2h[kc], bw.x, bw.y);
                    mma_bf16(C[nc], A2h[kc], bw.z, bw.w);
                    mma_bf16(C[nc], A2l[kc], bw.x, bw.y);
                }
            #pragma unroll
            for (int nc = 0; nc < 8; nc++) {
                float2 r0 = __ldg((const float2*)(nf + (size_t)n0 * 64 + nc * 8 + 2 * m));
                float2 r1 = __ldg((const float2*)(nf + (size_t)n1 * 64 + nc * 8 + 2 * m));
                *(float2*)(out_node + (size_t)n0 * 64 + nc * 8 + 2 * m) =
                    make_float2(r0.x + C[nc][0], r0.y + C[nc][1]);
                *(float2*)(out_node + (size_t)n1 * 64 + nc * 8 + 2 * m) =
                    make_float2(r1.x + C[nc][2], r1.y + C[nc][3]);
            }
        }
    }
}

// ---------------------------------------------------------------------------
// Edge kernel (R6 pipeline + C-init optimization: PQ/b2/b3 injected as C init)
// ---------------------------------------------------------------------------
__global__ __launch_bounds__(TPB, 1)
void edge_mlp_kernel(const float* __restrict__ ef,
                     const float* __restrict__ mW1, const float* __restrict__ mb1,
                     const float* __restrict__ mW2, const float* __restrict__ mb2,
                     const float* __restrict__ mW3, const float* __restrict__ mb3,
                     const int*   __restrict__ eidx,
                     float* __restrict__ agg)
{
    extern __shared__ char smem[];
    const int tid  = threadIdx.x;
    const int w    = tid >> 5;
    const int lane = tid & 31;
    const int m    = lane & 3;
    const int qrow = lane >> 2;

    STAGE_FRAGS(OFF_W1, 2, 16, KR_W1E, mW1, 128)
    STAGE_FRAGS(OFF_W2, 8, 16, KR_ID,  mW2, 128)
    STAGE_FRAGS(OFF_W3, 8, 8,  KR_ID,  mW3, 64)
    float* b1s = (float*)(smem + OFF_B1);
    float* b2s = (float*)(smem + OFF_B2);
    float* b3s = (float*)(smem + OFF_B3);
    if (tid < 128) { b1s[tid] = mb1[tid]; b2s[tid] = mb2[tid]; }
    if (tid < 64)  { b3s[tid] = mb3[tid]; }
    __syncthreads();

    float* pq = (float*)(smem + OFF_PQ + w * PQ_WARP_BYTES);   // [16][136]
    const float4 bv1 = ((const float4*)b1s)[lane];

    for (int tile = blockIdx.x; tile < N_TILES_E; tile += gridDim.x) {
        const int base_e = tile * TILE_E + w * 16;

        int2 se = make_int2(0, 0);
        if (lane < 16) se = ((const int2*)eidx)[base_e + lane];
        __syncwarp();

        // ---- stage PQ = P[src] + Q[dst] + b1 into warp-private smem ----
        #pragma unroll 4
        for (int r = 0; r < 16; r++) {
            int sr = __shfl_sync(0xffffffffu, se.x, r);
            int dr = __shfl_sync(0xffffffffu, se.y, r);
            float4 pv = __ldg((const float4*)g_P + (size_t)sr * 32 + lane);
            float4 qv = __ldg((const float4*)g_Q + (size_t)dr * 32 + lane);
            float4 o;
            o.x = pv.x + qv.x + bv1.x; o.y = pv.y + qv.y + bv1.y;
            o.z = pv.z + qv.z + bv1.z; o.w = pv.w + qv.w + bv1.w;
            *(float4*)(pq + r * 136 + lane * 4) = o;
        }
        __syncwarp();

        // ---- A1 fragments from ef (K=32) ----
        const float* e0p = ef + (size_t)(base_e + qrow) * 32;
        const float* e1p = ef + (size_t)(base_e + qrow + 8) * 32;
        uint32_t A1h[2][4], A1l[2][4];
        {
            float2 v00 = __ldg((const float2*)(e0p + 2 * m));
            float2 v01 = __ldg((const float2*)(e0p + 2 * m + 8));
            float2 v02 = __ldg((const float2*)(e0p + 2 * m + 16));
            float2 v03 = __ldg((const float2*)(e0p + 2 * m + 24));
            float2 v10 = __ldg((const float2*)(e1p + 2 * m));
            float2 v11 = __ldg((const float2*)(e1p + 2 * m + 8));
            float2 v12 = __ldg((const float2*)(e1p + 2 * m + 16));
            float2 v13 = __ldg((const float2*)(e1p + 2 * m + 24));
            bsplit2(v00.x, v00.y, A1h[0][0], A1l[0][0]);
            bsplit2(v10.x, v10.y, A1h[0][1], A1l[0][1]);
            bsplit2(v01.x, v01.y, A1h[0][2], A1l[0][2]);
            bsplit2(v11.x, v11.y, A1h[0][3], A1l[0][3]);
            bsplit2(v02.x, v02.y, A1h[1][0], A1l[1][0]);
            bsplit2(v12.x, v12.y, A1h[1][1], A1l[1][1]);
            bsplit2(v03.x, v03.y, A1h[1][2], A1l[1][2]);
            bsplit2(v13.x, v13.y, A1h[1][3], A1l[1][3]);
        }

        // ---- L1: C1 init = PQ frags; += ef@W1e ----
        float C1[16][4];
        #pragma unroll
        for (int nc = 0; nc < 16; nc++) {
            float2 p0 = *(const float2*)(pq + qrow * 136 + nc * 8 + 2 * m);
            float2 p1 = *(const float2*)(pq + (qrow + 8) * 136 + nc * 8 + 2 * m);
            C1[nc][0] = p0.x; C1[nc][1] = p0.y; C1[nc][2] = p1.x; C1[nc][3] = p1.y;
        }
        #pragma unroll
        for (int nc = 0; nc < 16; nc++)
            #pragma unroll
            for (int kc = 0; kc < 2; kc++) {
                uint4 bw = *(const uint4*)(smem + OFF_W1 + (((kc * 16 + nc) * 32) + lane) * 16);
                mma_bf16(C1[nc], A1h[kc], bw.x, bw.y);
                mma_bf16(C1[nc], A1h[kc], bw.z, bw.w);
                mma_bf16(C1[nc], A1l[kc], bw.x, bw.y);
            }

        // ---- h1 = relu(C1) -> A2 ----
        uint32_t A2h[8][4], A2l[8][4];
        #pragma unroll
        for (int j = 0; j < 8; j++) {
            float x00 = fmaxf(C1[2 * j][0], 0.f),     x01 = fmaxf(C1[2 * j][1], 0.f);
            float x10 = fmaxf(C1[2 * j][2], 0.f),     x11 = fmaxf(C1[2 * j][3], 0.f);
            float y00 = fmaxf(C1[2 * j + 1][0], 0.f), y01 = fmaxf(C1[2 * j + 1][1], 0.f);
            float y10 = fmaxf(C1[2 * j + 1][2], 0.f), y11 = fmaxf(C1[2 * j + 1][3], 0.f);
            bsplit2(x00, x01, A2h[j][0], A2l[j][0]);
            bsplit2(x10, x11, A2h[j][1], A2l[j][1]);
            bsplit2(y00, y01, A2h[j][2], A2l[j][2]);
            bsplit2(y10, y11, A2h[j][3], A2l[j][3]);
        }

        // ---- L2: C2 init = b2; += h1@W2 ----
        float C2[16][4];
        #pragma unroll
        for (int nc = 0; nc < 16; nc++) {
            float2 b = *(const float2*)(b2s + nc * 8 + 2 * m);
            C2[nc][0] = b.x; C2[nc][1] = b.y; C2[nc][2] = b.x; C2[nc][3] = b.y;
        }
        #pragma unroll
        for (int nc = 0; nc < 16; nc++)
            #pragma unroll
            for (int kc = 0; kc < 8; kc++) {
                uint4 bw = *(const uint4*)(smem + OFF_W2 + (((kc * 16 + nc) * 32) + lane) * 16);
                mma_bf16(C2[nc], A2h[kc], bw.x, bw.y);
                mma_bf16(C2[nc], A2h[kc], bw.z, bw.w);
                mma_bf16(C2[nc], A2l[kc], bw.x, bw.y);
            }

        // ---- h2 = relu(C2) -> A3 ----
        uint32_t A3h[8][4], A3l[8][4];
        #pragma unroll
        for (int j = 0; j < 8; j++) {
            float x00 = fmaxf(C2[2 * j][0], 0.f),     x01 = fmaxf(C2[2 * j][1], 0.f);
            float x10 = fmaxf(C2[2 * j][2], 0.f),     x11 = fmaxf(C2[2 * j][3], 0.f);
            float y00 = fmaxf(C2[2 * j + 1][0], 0.f), y01 = fmaxf(C2[2 * j + 1][1], 0.f);
            float y10 = fmaxf(C2[2 * j + 1][2], 0.f), y11 = fmaxf(C2[2 * j + 1][3], 0.f);
            bsplit2(x00, x01, A3h[j][0], A3l[j][0]);
            bsplit2(x10, x11, A3h[j][1], A3l[j][1]);
            bsplit2(y00, y01, A3h[j][2], A3l[j][2]);
            bsplit2(y10, y11, A3h[j][3], A3l[j][3]);
        }

        // ---- L3: C3 init = b3; += h2@W3 ----
        float C3[8][4];
        #pragma unroll
        for (int nc = 0; nc < 8; nc++) {
            float2 b = *(const float2*)(b3s + nc * 8 + 2 * m);
            C3[nc][0] = b.x; C3[nc][1] = b.y; C3[nc][2] = b.x; C3[nc][3] = b.y;
        }
        #pragma unroll
        for (int nc = 0; nc < 8; nc++)
            #pragma unroll
            for (int kc = 0; kc < 8; kc++) {
                uint4 bw = *(const uint4*)(smem + OFF_W3 + (((kc * 8 + nc) * 32) + lane) * 16);
                mma_bf16(C3[nc], A3h[kc], bw.x, bw.y);
                mma_bf16(C3[nc], A3h[kc], bw.z, bw.w);
                mma_bf16(C3[nc], A3l[kc], bw.x, bw.y);
            }

        // ---- m = C3 -> msg smem (reuse pq region, stride 72) ----
        float* msg = pq;
        __syncwarp();
        #pragma unroll
        for (int nc = 0; nc < 8; nc++) {
            *(float2*)(msg + qrow * 72 + 8 * nc + 2 * m) = make_float2(C3[nc][0], C3[nc][1]);
            *(float2*)(msg + (qrow + 8) * 72 + 8 * nc + 2 * m) = make_float2(C3[nc][2], C3[nc][3]);
        }
        __syncwarp();

        // ---- scatter: 16 edges x 16 float4 atomics ----
        #pragma unroll
        for (int it = 0; it < 8; it++) {
            int slot = it * 32 + lane;
            int e = slot >> 4, q = slot & 15;
            float4 v = *(const float4*)(msg + e * 72 + q * 4);
            int dn = __shfl_sync(0xffffffffu, se.y, e);
            atomicAdd(((float4*)(agg + (size_t)dn * 64)) + q, v);
        }
    }
}

extern "C" void kernel_launch(void* const* d_in, const int* in_sizes, int n_in,
                              void* d_out, int out_size)
{
    const float* nf  = (const float*)d_in[0];
    const float* ef  = (const float*)d_in[1];
    const float* stx = (const float*)d_in[2];
    const float* mW1 = (const float*)d_in[3];
    const float* mb1 = (const float*)d_in[4];
    const float* mW2 = (const float*)d_in[5];
    const float* mb2 = (const float*)d_in[6];
    const float* mW3 = (const float*)d_in[7];
    const float* mb3 = (const float*)d_in[8];
    const float* uW1 = (const float*)d_in[9];
    const float* ub1 = (const float*)d_in[10];
    const float* uW2 = (const float*)d_in[11];
    const float* ub2 = (const float*)d_in[12];
    const int*  eidx = (const int*)d_in[13];

    float* out_node = (float*)d_out;
    float* agg      = out_node + (size_t)N_NODES_C * 64;

    cudaFuncSetAttribute(edge_mlp_kernel,
                         cudaFuncAttributeMaxDynamicSharedMemorySize, EDGE_SMEM_BYTES);
    cudaFuncSetAttribute(node_fused_kernel,
                         cudaFuncAttributeMaxDynamicSharedMemorySize, NODEF_SMEM_BYTES);

    int dev = 0;
    cudaGetDevice(&dev);
    int sms = 148;
    cudaDeviceGetAttribute(&sms, cudaDevAttrMultiProcessorCount, dev);

    cudaMemsetAsync(agg, 0, (size_t)N_NODES_C * 64 * sizeof(float));
    node_fused_kernel<<<sms, TPB, NODEF_SMEM_BYTES>>>(nf, stx, mW1, uW1, ub1, uW2, ub2,
                                                      out_node);
    edge_mlp_kernel<<<sms, TPB, EDGE_SMEM_BYTES>>>(ef, mW1, mb1, mW2, mb2,
                                                   mW3, mb3, eidx, agg);
}

// round 8
// speedup vs baseline: 8.0639x; 1.0336x over previous
#include <cuda_runtime.h>
#include <cuda_bf16.h>
#include <cstdint>

#define N_NODES_C 50000
#define N_EDGES_C 800000

#define TPB_N 256          // node kernel: 8 warps
#define TPB_E 384          // edge kernel: 12 warps
#define NW_E 12
#define N_WT_EDGE (N_EDGES_C / 16)          // 50000 warp-tiles
#define N_WT_NODE (N_NODES_C / 16)          // 3125 warp-tiles

// Per-node layer-1 partials (scratch; no allocation allowed)
__device__ float g_P[(size_t)N_NODES_C * 128];   // nf@W1[0:64] + st@W1[160:192]
__device__ float g_Q[(size_t)N_NODES_C * 128];   // nf@W1[64:128]

// ---------------- edge kernel SMEM (bytes) ----------------
#define OFF_W1 0                          // kc=2, nc=16 : 16384
#define OFF_W2 16384                      // kc=8, nc=16 : 65536
#define OFF_W3 81920                      // kc=8, nc=8  : 32768
#define OFF_B1 114688                     // 128 f32
#define OFF_B2 115200                     // 128 f32
#define OFF_B3 115712                     // 64 f32
#define OFF_PQ 115968                     // 12 warps * 16 rows * 136 f32
#define PQ_WARP_BYTES (16*136*4)          // 8704
#define EDGE_SMEM_BYTES (OFF_PQ + NW_E*PQ_WARP_BYTES)   // 220416

// ---------------- fused node kernel SMEM (bytes) ----------------
#define NOFF_BP  0
#define NOFF_BQ  49152
#define NOFF_BU1 81920
#define NOFF_BU2 131072
#define NOFF_UB1 163840
#define NOFF_UB2 164352
#define NODEF_SMEM_BYTES (164608)

// bf16 split of a float pair -> packed bf16x2 (low half = first arg / even idx)
static __device__ __forceinline__ void bsplit2(float x0, float x1,
                                               uint32_t& hi, uint32_t& lo) {
    uint32_t h;
    asm("cvt.rn.bf16x2.f32 %0, %1, %2;" : "=r"(h) : "f"(x1), "f"(x0));
    float r0 = x0 - __uint_as_float(h << 16);
    float r1 = x1 - __uint_as_float(h & 0xFFFF0000u);
    uint32_t l;
    asm("cvt.rn.bf16x2.f32 %0, %1, %2;" : "=r"(l) : "f"(r1), "f"(r0));
    hi = h; lo = l;
}

// D += A(16x16 bf16) * B(16x8 bf16), fp32 accum
static __device__ __forceinline__ void mma_bf16(float* d, const uint32_t* a,
                                                uint32_t b0, uint32_t b1) {
    asm volatile("mma.sync.aligned.m16n8k16.row.col.f32.bf16.bf16.f32 "
        "{%0,%1,%2,%3}, {%4,%5,%6,%7}, {%8,%9}, {%0,%1,%2,%3};"
        : "+f"(d[0]), "+f"(d[1]), "+f"(d[2]), "+f"(d[3])
        : "r"(a[0]), "r"(a[1]), "r"(a[2]), "r"(a[3]), "r"(b0), "r"(b1));
}

// Stage one weight B-fragment set (hi/lo interleaved uint4) from row-major W[k][n].
#define STAGE_FRAGS(dst_off, KC, NC, KROW_EXPR, SRC_PTR, SRC_N, STRIDE)         \
    for (int idx = tid; idx < (KC) * (NC) * 32; idx += (STRIDE)) {              \
        int T = idx & 31, nc = (idx >> 5) % (NC), kc = idx / ((NC) * 32);       \
        int n = nc * 8 + (T >> 2);                                              \
        int k0 = kc * 16 + (T & 3) * 2;                                         \
        int ka = (KROW_EXPR(k0)), kb = (KROW_EXPR(k0 + 1));                     \
        int kd = (KROW_EXPR(k0 + 8)), ke = (KROW_EXPR(k0 + 9));                 \
        float w00 = (SRC_PTR)[ka * (SRC_N) + n], w01 = (SRC_PTR)[kb * (SRC_N) + n]; \
        float w10 = (SRC_PTR)[kd * (SRC_N) + n], w11 = (SRC_PTR)[ke * (SRC_N) + n]; \
        uint32_t b0h, b0l, b1h, b1l;                                            \
        bsplit2(w00, w01, b0h, b0l);                                            \
        bsplit2(w10, w11, b1h, b1l);                                            \
        *(uint4*)(smem + (dst_off) + idx * 16) = make_uint4(b0h, b1h, b0l, b1l); \
    }

#define KR_ID(k)    (k)
#define KR_W1E(k)   (128 + (k))
#define KR_P(k)     ((k) < 64 ? (k) : (k) + 96)
#define KR_Q(k)     (64 + (k))

// ---------------------------------------------------------------------------
// Fused node kernel (unchanged from R7 — proven)
// ---------------------------------------------------------------------------
__global__ __launch_bounds__(TPB_N, 1)
void node_fused_kernel(const float* __restrict__ nf,
                       const float* __restrict__ stx,
                       const float* __restrict__ mW1,
                       const float* __restrict__ uW1, const float* __restrict__ ub1,
                       const float* __restrict__ uW2, const float* __restrict__ ub2,
                       float* __restrict__ out_node)
{
    extern __shared__ char smem[];
    const int tid  = threadIdx.x;
    const int w    = tid >> 5;
    const int lane = tid & 31;
    const int m    = lane & 3;
    const int qrow = lane >> 2;

    STAGE_FRAGS(NOFF_BP,  6, 16, KR_P,  mW1, 128, TPB_N)
    STAGE_FRAGS(NOFF_BQ,  4, 16, KR_Q,  mW1, 128, TPB_N)
    STAGE_FRAGS(NOFF_BU1, 6, 16, KR_ID, uW1, 128, TPB_N)
    STAGE_FRAGS(NOFF_BU2, 8, 8,  KR_ID, uW2, 64,  TPB_N)
    float* ub1s = (float*)(smem + NOFF_UB1);
    float* ub2s = (float*)(smem + NOFF_UB2);
    if (tid < 128) ub1s[tid] = ub1[tid];
    if (tid < 64)  ub2s[tid] = ub2[tid];
    __syncthreads();

    const int gw = blockIdx.x * 8 + w;
    const int gstride = gridDim.x * 8;

    for (int wt = gw; wt < N_WT_NODE; wt += gstride) {
        const int n0 = wt * 16 + qrow;
        const int n1 = n0 + 8;

        uint32_t xh[6][4], xl[6][4];
        #pragma unroll
        for (int kc = 0; kc < 4; kc++) {
            float2 v0  = __ldg((const float2*)(nf + (size_t)n0 * 64 + kc * 16 + 2 * m));
            float2 v1  = __ldg((const float2*)(nf + (size_t)n1 * 64 + kc * 16 + 2 * m));
            float2 v0b = __ldg((const float2*)(nf + (size_t)n0 * 64 + kc * 16 + 8 + 2 * m));
            float2 v1b = __ldg((const float2*)(nf + (size_t)n1 * 64 + kc * 16 + 8 + 2 * m));
            bsplit2(v0.x,  v0.y,  xh[kc][0], xl[kc][0]);
            bsplit2(v1.x,  v1.y,  xh[kc][1], xl[kc][1]);
            bsplit2(v0b.x, v0b.y, xh[kc][2], xl[kc][2]);
            bsplit2(v1b.x, v1b.y, xh[kc][3], xl[kc][3]);
        }
        #pragma unroll
        for (int kc = 4; kc < 6; kc++) {
            int c = (kc - 4) * 16;
            float2 v0  = __ldg((const float2*)(stx + (size_t)n0 * 32 + c + 2 * m));
            float2 v1  = __ldg((const float2*)(stx + (size_t)n1 * 32 + c + 2 * m));
            float2 v0b = __ldg((const float2*)(stx + (size_t)n0 * 32 + c + 8 + 2 * m));
            float2 v1b = __ldg((const float2*)(stx + (size_t)n1 * 32 + c + 8 + 2 * m));
            bsplit2(v0.x,  v0.y,  xh[kc][0], xl[kc][0]);
            bsplit2(v1.x,  v1.y,  xh[kc][1], xl[kc][1]);
            bsplit2(v0b.x, v0b.y, xh[kc][2], xl[kc][2]);
            bsplit2(v1b.x, v1b.y, xh[kc][3], xl[kc][3]);
        }

        {   // P (K=96)
            #pragma unroll
            for (int nc = 0; nc < 16; nc++) {
                float C[4] = {0.f, 0.f, 0.f, 0.f};
                #pragma unroll
                for (int kc = 0; kc < 6; kc++) {
                    uint4 bw = *(const uint4*)(smem + NOFF_BP + (((kc * 16 + nc) * 32) + lane) * 16);
                    mma_bf16(C, xh[kc], bw.x, bw.y);
                    mma_bf16(C, xh[kc], bw.z, bw.w);
                    mma_bf16(C, xl[kc], bw.x, bw.y);
                }
                *(float2*)(g_P + (size_t)n0 * 128 + nc * 8 + 2 * m) = make_float2(C[0], C[1]);
                *(float2*)(g_P + (size_t)n1 * 128 + nc * 8 + 2 * m) = make_float2(C[2], C[3]);
            }
        }
        {   // Q (K=64)
            #pragma unroll
            for (int nc = 0; nc < 16; nc++) {
                float C[4] = {0.f, 0.f, 0.f, 0.f};
                #pragma unroll
                for (int kc = 0; kc < 4; kc++) {
                    uint4 bw = *(const uint4*)(smem + NOFF_BQ + (((kc * 16 + nc) * 32) + lane) * 16);
                    mma_bf16(C, xh[kc], bw.x, bw.y);
                    mma_bf16(C, xh[kc], bw.z, bw.w);
                    mma_bf16(C, xl[kc], bw.x, bw.y);
                }
                *(float2*)(g_Q + (size_t)n0 * 128 + nc * 8 + 2 * m) = make_float2(C[0], C[1]);
                *(float2*)(g_Q + (size_t)n1 * 128 + nc * 8 + 2 * m) = make_float2(C[2], C[3]);
            }
        }
        uint32_t A2h[8][4], A2l[8][4];
        {   // h = relu(x@uW1 + ub1)
            #pragma unroll
            for (int j = 0; j < 8; j++) {
                float2 ba = *(const float2*)(ub1s + (2 * j) * 8 + 2 * m);
                float2 bb = *(const float2*)(ub1s + (2 * j + 1) * 8 + 2 * m);
                float Ca[4] = {ba.x, ba.y, ba.x, ba.y};
                float Cb[4] = {bb.x, bb.y, bb.x, bb.y};
                #pragma unroll
                for (int kc = 0; kc < 6; kc++) {
                    uint4 ba4 = *(const uint4*)(smem + NOFF_BU1 + (((kc * 16 + 2 * j) * 32) + lane) * 16);
                    uint4 bb4 = *(const uint4*)(smem + NOFF_BU1 + (((kc * 16 + 2 * j + 1) * 32) + lane) * 16);
                    mma_bf16(Ca, xh[kc], ba4.x, ba4.y);
                    mma_bf16(Ca, xh[kc], ba4.z, ba4.w);
                    mma_bf16(Ca, xl[kc], ba4.x, ba4.y);
                    mma_bf16(Cb, xh[kc], bb4.x, bb4.y);
                    mma_bf16(Cb, xh[kc], bb4.z, bb4.w);
                    mma_bf16(Cb, xl[kc], bb4.x, bb4.y);
                }
                bsplit2(fmaxf(Ca[0], 0.f), fmaxf(Ca[1], 0.f), A2h[j][0], A2l[j][0]);
                bsplit2(fmaxf(Ca[2], 0.f), fmaxf(Ca[3], 0.f), A2h[j][1], A2l[j][1]);
                bsplit2(fmaxf(Cb[0], 0.f), fmaxf(Cb[1], 0.f), A2h[j][2], A2l[j][2]);
                bsplit2(fmaxf(Cb[2], 0.f), fmaxf(Cb[3], 0.f), A2h[j][3], A2l[j][3]);
            }
        }
        {   // out = nf + h@uW2 + ub2
            #pragma unroll
            for (int nc = 0; nc < 8; nc++) {
                float2 b = *(const float2*)(ub2s + nc * 8 + 2 * m);
                float C[4] = {b.x, b.y, b.x, b.y};
                #pragma unroll
                for (int kc = 0; kc < 8; kc++) {
                    uint4 bw = *(const uint4*)(smem + NOFF_BU2 + (((kc * 8 + nc) * 32) + lane) * 16);
                    mma_bf16(C, A2h[kc], bw.x, bw.y);
                    mma_bf16(C, A2h[kc], bw.z, bw.w);
                    mma_bf16(C, A2l[kc], bw.x, bw.y);
                }
                float2 r0 = __ldg((const float2*)(nf + (size_t)n0 * 64 + nc * 8 + 2 * m));
                float2 r1 = __ldg((const float2*)(nf + (size_t)n1 * 64 + nc * 8 + 2 * m));
                *(float2*)(out_node + (size_t)n0 * 64 + nc * 8 + 2 * m) =
                    make_float2(r0.x + C[0], r0.y + C[1]);
                *(float2*)(out_node + (size_t)n1 * 64 + nc * 8 + 2 * m) =
                    make_float2(r1.x + C[2], r1.y + C[3]);
            }
        }
    }
}

// ---------------------------------------------------------------------------
// Edge kernel: 12 warps/CTA, global warp-tile loop (16 edges per warp-tile),
// incremental per-nc-pair accumulation to cut register pressure.
// ---------------------------------------------------------------------------
__global__ __launch_bounds__(TPB_E, 1)
void edge_mlp_kernel(const float* __restrict__ ef,
                     const float* __restrict__ mW1, const float* __restrict__ mb1,
                     const float* __restrict__ mW2, const float* __restrict__ mb2,
                     const float* __restrict__ mW3, const float* __restrict__ mb3,
                     const int*   __restrict__ eidx,
                     float* __restrict__ agg)
{
    extern __shared__ char smem[];
    const int tid  = threadIdx.x;
    const int w    = tid >> 5;
    const int lane = tid & 31;
    const int m    = lane & 3;
    const int qrow = lane >> 2;

    STAGE_FRAGS(OFF_W1, 2, 16, KR_W1E, mW1, 128, TPB_E)
    STAGE_FRAGS(OFF_W2, 8, 16, KR_ID,  mW2, 128, TPB_E)
    STAGE_FRAGS(OFF_W3, 8, 8,  KR_ID,  mW3, 64,  TPB_E)
    float* b1s = (float*)(smem + OFF_B1);
    float* b2s = (float*)(smem + OFF_B2);
    float* b3s = (float*)(smem + OFF_B3);
    if (tid < 128) { b1s[tid] = mb1[tid]; b2s[tid] = mb2[tid]; }
    if (tid < 64)  { b3s[tid] = mb3[tid]; }
    __syncthreads();

    float* pq = (float*)(smem + OFF_PQ + w * PQ_WARP_BYTES);   // [16][136]
    const float4 bv1 = ((const float4*)b1s)[lane];

    const int gw = blockIdx.x * NW_E + w;
    const int gstride = gridDim.x * NW_E;

    for (int wt = gw; wt < N_WT_EDGE; wt += gstride) {
        const int base_e = wt * 16;

        int2 se = make_int2(0, 0);
        if (lane < 16) se = ((const int2*)eidx)[base_e + lane];
        __syncwarp();    // also fences pq/msg reuse from previous tile

        // ---- prefetch ef (K=32) into regs: both gather streams in flight ----
        const float* e0p = ef + (size_t)(base_e + qrow) * 32;
        const float* e1p = ef + (size_t)(base_e + qrow + 8) * 32;
        float2 v00 = __ldg((const float2*)(e0p + 2 * m));
        float2 v01 = __ldg((const float2*)(e0p + 2 * m + 8));
        float2 v02 = __ldg((const float2*)(e0p + 2 * m + 16));
        float2 v03 = __ldg((const float2*)(e0p + 2 * m + 24));
        float2 v10 = __ldg((const float2*)(e1p + 2 * m));
        float2 v11 = __ldg((const float2*)(e1p + 2 * m + 8));
        float2 v12 = __ldg((const float2*)(e1p + 2 * m + 16));
        float2 v13 = __ldg((const float2*)(e1p + 2 * m + 24));

        // ---- stage PQ = P[src] + Q[dst] + b1 into warp-private smem ----
        #pragma unroll 4
        for (int r = 0; r < 16; r++) {
            int sr = __shfl_sync(0xffffffffu, se.x, r);
            int dr = __shfl_sync(0xffffffffu, se.y, r);
            float4 pv = __ldg((const float4*)g_P + (size_t)sr * 32 + lane);
            float4 qv = __ldg((const float4*)g_Q + (size_t)dr * 32 + lane);
            float4 o;
            o.x = pv.x + qv.x + bv1.x; o.y = pv.y + qv.y + bv1.y;
            o.z = pv.z + qv.z + bv1.z; o.w = pv.w + qv.w + bv1.w;
            *(float4*)(pq + r * 136 + lane * 4) = o;
        }
        __syncwarp();

        // ---- A1 fragments ----
        uint32_t A1h[2][4], A1l[2][4];
        bsplit2(v00.x, v00.y, A1h[0][0], A1l[0][0]);
        bsplit2(v10.x, v10.y, A1h[0][1], A1l[0][1]);
        bsplit2(v01.x, v01.y, A1h[0][2], A1l[0][2]);
        bsplit2(v11.x, v11.y, A1h[0][3], A1l[0][3]);
        bsplit2(v02.x, v02.y, A1h[1][0], A1l[1][0]);
        bsplit2(v12.x, v12.y, A1h[1][1], A1l[1][1]);
        bsplit2(v03.x, v03.y, A1h[1][2], A1l[1][2]);
        bsplit2(v13.x, v13.y, A1h[1][3], A1l[1][3]);

        // ---- L1 (incremental): C init = PQ; += ef@W1e; -> A2 frags ----
        uint32_t A2h[8][4], A2l[8][4];
        #pragma unroll
        for (int j = 0; j < 8; j++) {
            float2 pa0 = *(const float2*)(pq + qrow * 136 + 16 * j + 2 * m);
            float2 pa1 = *(const float2*)(pq + (qrow + 8) * 136 + 16 * j + 2 * m);
            float2 pb0 = *(const float2*)(pq + qrow * 136 + 16 * j + 8 + 2 * m);
            float2 pb1 = *(const float2*)(pq + (qrow + 8) * 136 + 16 * j + 8 + 2 * m);
            float Ca[4] = {pa0.x, pa0.y, pa1.x, pa1.y};
            float Cb[4] = {pb0.x, pb0.y, pb1.x, pb1.y};
            #pragma unroll
            for (int kc = 0; kc < 2; kc++) {
                uint4 ba = *(const uint4*)(smem + OFF_W1 + (((kc * 16 + 2 * j) * 32) + lane) * 16);
                uint4 bb = *(const uint4*)(smem + OFF_W1 + (((kc * 16 + 2 * j + 1) * 32) + lane) * 16);
                mma_bf16(Ca, A1h[kc], ba.x, ba.y);
                mma_bf16(Ca, A1h[kc], ba.z, ba.w);
                mma_bf16(Ca, A1l[kc], ba.x, ba.y);
                mma_bf16(Cb, A1h[kc], bb.x, bb.y);
                mma_bf16(Cb, A1h[kc], bb.z, bb.w);
                mma_bf16(Cb, A1l[kc], bb.x, bb.y);
            }
            bsplit2(fmaxf(Ca[0], 0.f), fmaxf(Ca[1], 0.f), A2h[j][0], A2l[j][0]);
            bsplit2(fmaxf(Ca[2], 0.f), fmaxf(Ca[3], 0.f), A2h[j][1], A2l[j][1]);
            bsplit2(fmaxf(Cb[0], 0.f), fmaxf(Cb[1], 0.f), A2h[j][2], A2l[j][2]);
            bsplit2(fmaxf(Cb[2], 0.f), fmaxf(Cb[3], 0.f), A2h[j][3], A2l[j][3]);
        }

        // ---- L2 (incremental): C init = b2; += h1@W2; -> A3 frags ----
        uint32_t A3h[8][4], A3l[8][4];
        #pragma unroll
        for (int j = 0; j < 8; j++) {
            float2 ba2 = *(const float2*)(b2s + (2 * j) * 8 + 2 * m);
            float2 bb2 = *(const float2*)(b2s + (2 * j + 1) * 8 + 2 * m);
            float Ca[4] = {ba2.x, ba2.y, ba2.x, ba2.y};
            float Cb[4] = {bb2.x, bb2.y, bb2.x, bb2.y};
            #pragma unroll
            for (int kc = 0; kc < 8; kc++) {
                uint4 ba = *(const uint4*)(smem + OFF_W2 + (((kc * 16 + 2 * j) * 32) + lane) * 16);
                uint4 bb = *(const uint4*)(smem + OFF_W2 + (((kc * 16 + 2 * j + 1) * 32) + lane) * 16);
                mma_bf16(Ca, A2h[kc], ba.x, ba.y);
                mma_bf16(Ca, A2h[kc], ba.z, ba.w);
                mma_bf16(Ca, A2l[kc], ba.x, ba.y);
                mma_bf16(Cb, A2h[kc], bb.x, bb.y);
                mma_bf16(Cb, A2h[kc], bb.z, bb.w);
                mma_bf16(Cb, A2l[kc], bb.x, bb.y);
            }
            bsplit2(fmaxf(Ca[0], 0.f), fmaxf(Ca[1], 0.f), A3h[j][0], A3l[j][0]);
            bsplit2(fmaxf(Ca[2], 0.f), fmaxf(Ca[3], 0.f), A3h[j][1], A3l[j][1]);
            bsplit2(fmaxf(Cb[0], 0.f), fmaxf(Cb[1], 0.f), A3h[j][2], A3l[j][2]);
            bsplit2(fmaxf(Cb[2], 0.f), fmaxf(Cb[3], 0.f), A3h[j][3], A3l[j][3]);
        }

        // ---- L3 (incremental): C init = b3; += h2@W3; -> msg smem ----
        float* msg = pq;
        __syncwarp();   // pq reads (L1 init) complete before msg overwrite
        #pragma unroll
        for (int nc = 0; nc < 8; nc++) {
            float2 b = *(const float2*)(b3s + nc * 8 + 2 * m);
            float C[4] = {b.x, b.y, b.x, b.y};
            #pragma unroll
            for (int kc = 0; kc < 8; kc++) {
                uint4 bw = *(const uint4*)(smem + OFF_W3 + (((kc * 8 + nc) * 32) + lane) * 16);
                mma_bf16(C, A3h[kc], bw.x, bw.y);
                mma_bf16(C, A3h[kc], bw.z, bw.w);
                mma_bf16(C, A3l[kc], bw.x, bw.y);
            }
            *(float2*)(msg + qrow * 72 + 8 * nc + 2 * m) = make_float2(C[0], C[1]);
            *(float2*)(msg + (qrow + 8) * 72 + 8 * nc + 2 * m) = make_float2(C[2], C[3]);
        }
        __syncwarp();

        // ---- scatter: 16 edges x 16 float4 atomics ----
        #pragma unroll
        for (int it = 0; it < 8; it++) {
            int slot = it * 32 + lane;
            int e = slot >> 4, q = slot & 15;
            float4 v = *(const float4*)(msg + e * 72 + q * 4);
            int dn = __shfl_sync(0xffffffffu, se.y, e);
            atomicAdd(((float4*)(agg + (size_t)dn * 64)) + q, v);
        }
    }
}

extern "C" void kernel_launch(void* const* d_in, const int* in_sizes, int n_in,
                              void* d_out, int out_size)
{
    const float* nf  = (const float*)d_in[0];
    const float* ef  = (const float*)d_in[1];
    const float* stx = (const float*)d_in[2];
    const float* mW1 = (const float*)d_in[3];
    const float* mb1 = (const float*)d_in[4];
    const float* mW2 = (const float*)d_in[5];
    const float* mb2 = (const float*)d_in[6];
    const float* mW3 = (const float*)d_in[7];
    const float* mb3 = (const float*)d_in[8];
    const float* uW1 = (const float*)d_in[9];
    const float* ub1 = (const float*)d_in[10];
    const float* uW2 = (const float*)d_in[11];
    const float* ub2 = (const float*)d_in[12];
    const int*  eidx = (const int*)d_in[13];

    float* out_node = (float*)d_out;
    float* agg      = out_node + (size_t)N_NODES_C * 64;

    cudaFuncSetAttribute(edge_mlp_kernel,
                         cudaFuncAttributeMaxDynamicSharedMemorySize, EDGE_SMEM_BYTES);
    cudaFuncSetAttribute(node_fused_kernel,
                         cudaFuncAttributeMaxDynamicSharedMemorySize, NODEF_SMEM_BYTES);

    int dev = 0;
    cudaGetDevice(&dev);
    int sms = 148;
    cudaDeviceGetAttribute(&sms, cudaDevAttrMultiProcessorCount, dev);

    cudaMemsetAsync(agg, 0, (size_t)N_NODES_C * 64 * sizeof(float));
    node_fused_kernel<<<sms, TPB_N, NODEF_SMEM_BYTES>>>(nf, stx, mW1, uW1, ub1, uW2, ub2,
                                                        out_node);
    edge_mlp_kernel<<<sms, TPB_E, EDGE_SMEM_BYTES>>>(ef, mW1, mb1, mW2, mb2,
                                                     mW3, mb3, eidx, agg);
}